// round 2
// baseline (speedup 1.0000x reference)
#include <cuda_runtime.h>

#define BB 4
#define SS 2048
#define HH 1024
#define NH 16
#define DH 64
#define MTOT (BB*SS)   // 8192

// Scratch (allocation-free rule: __device__ globals)
__device__ float g_q[BB*NH*SS*DH];     // 32 MB, [b,h,s,d], pre-scaled by 1/8
__device__ float g_k[BB*NH*SS*DH];     // 32 MB
__device__ float g_v[BB*NH*SS*DH];     // 32 MB
__device__ float g_ctx[BB*SS*HH];      // 32 MB, [b,s,h*64+d]

// ---------------------------------------------------------------------------
// GEMM: out = (X[M,1024] @ W[1024,1024] + bias) * scale
// BM=128, BN=64, BK=16, 256 threads, 8x4 microtile.
// splitHead=1: write to [b, h=blockN, s, d] layout (BN == DH == 64).
// splitHead=0: write plain row-major [M, 1024].
// ---------------------------------------------------------------------------
#define BM 128
#define BN 64
#define BK 16

__global__ __launch_bounds__(256) void gemm_k(
    const float* __restrict__ X, const float* __restrict__ W,
    const float* __restrict__ bias, float* __restrict__ out,
    float scale, int splitHead)
{
    __shared__ float As[BK][BM];
    __shared__ float Bs[BK][BN];
    const int tid = threadIdx.x;
    const int tx = tid & 15;          // 0..15 -> 4 cols each
    const int ty = tid >> 4;          // 0..15 -> 8 rows each
    const int m0 = blockIdx.y * BM;
    const int n0 = blockIdx.x * BN;

    float acc[8][4];
    #pragma unroll
    for (int i = 0; i < 8; i++)
        #pragma unroll
        for (int j = 0; j < 4; j++) acc[i][j] = 0.f;

    for (int k0 = 0; k0 < HH; k0 += BK) {
        // Load A tile 128x16 (2 float4 per thread), store transposed
        #pragma unroll
        for (int p = 0; p < 2; p++) {
            int r  = (tid >> 2) + p * 64;
            int c4 = (tid & 3) * 4;
            float4 a = *(const float4*)&X[(size_t)(m0 + r) * HH + k0 + c4];
            As[c4 + 0][r] = a.x;
            As[c4 + 1][r] = a.y;
            As[c4 + 2][r] = a.z;
            As[c4 + 3][r] = a.w;
        }
        // Load B tile 16x64 (1 float4 per thread)
        {
            int r  = tid >> 4;
            int c4 = (tid & 15) * 4;
            *(float4*)&Bs[r][c4] = *(const float4*)&W[(size_t)(k0 + r) * HH + n0 + c4];
        }
        __syncthreads();
        #pragma unroll
        for (int k = 0; k < BK; k++) {
            float4 b4 = *(float4*)&Bs[k][tx * 4];
            float4 a0 = *(float4*)&As[k][ty * 8];
            float4 a1 = *(float4*)&As[k][ty * 8 + 4];
            float av[8] = {a0.x, a0.y, a0.z, a0.w, a1.x, a1.y, a1.z, a1.w};
            float bv[4] = {b4.x, b4.y, b4.z, b4.w};
            #pragma unroll
            for (int i = 0; i < 8; i++)
                #pragma unroll
                for (int j = 0; j < 4; j++)
                    acc[i][j] = fmaf(av[i], bv[j], acc[i][j]);
        }
        __syncthreads();
    }

    float bb[4];
    #pragma unroll
    for (int j = 0; j < 4; j++) bb[j] = bias[n0 + tx * 4 + j];

    #pragma unroll
    for (int i = 0; i < 8; i++) {
        int m = m0 + ty * 8 + i;
        float4 r;
        r.x = (acc[i][0] + bb[0]) * scale;
        r.y = (acc[i][1] + bb[1]) * scale;
        r.z = (acc[i][2] + bb[2]) * scale;
        r.w = (acc[i][3] + bb[3]) * scale;
        if (splitHead) {
            int b_ = m >> 11;            // /S
            int s_ = m & (SS - 1);
            int h_ = blockIdx.x;         // BN==DH
            float* dst = &out[(((size_t)(b_ * NH + h_)) * SS + s_) * DH + tx * 4];
            *(float4*)dst = r;
        } else {
            *(float4*)&out[(size_t)m * HH + n0 + tx * 4] = r;
        }
    }
}

// ---------------------------------------------------------------------------
// Flash attention: one thread per query row, 128 rows/CTA, 32-key tiles.
// Q pre-scaled by 1/sqrt(DH). Writes ctx in [b, s, h*64+d] layout.
// ---------------------------------------------------------------------------
#define ABM 128
#define ABN 32

__global__ __launch_bounds__(128) void attn_k(
    const float* __restrict__ Q, const float* __restrict__ K,
    const float* __restrict__ V, float* __restrict__ Ctx)
{
    __shared__ float Ks[ABN][DH];
    __shared__ float Vs[ABN][DH];
    const int t  = threadIdx.x;
    const int bh = blockIdx.y;               // 0..63
    const int b_ = bh >> 4;
    const int h_ = bh & 15;
    const int row = blockIdx.x * ABM + t;    // query index within S

    const float* qrow = Q + ((size_t)bh * SS + row) * DH;
    float4 q[16];
    #pragma unroll
    for (int c = 0; c < 16; c++) q[c] = *(const float4*)&qrow[c * 4];

    float4 o[16];
    #pragma unroll
    for (int c = 0; c < 16; c++) { o[c].x = o[c].y = o[c].z = o[c].w = 0.f; }
    float mmax = -1e30f, lsum = 0.f;

    const float* Kb = K + (size_t)bh * SS * DH;
    const float* Vb = V + (size_t)bh * SS * DH;

    for (int kt = 0; kt < SS; kt += ABN) {
        __syncthreads();
        // load K,V tiles: 32x64 floats each = 512 float4; 128 threads -> 4 each
        #pragma unroll
        for (int p = 0; p < 4; p++) {
            int idx = t + p * 128;           // 0..511
            int j = idx >> 4, c = (idx & 15) * 4;
            *(float4*)&Ks[j][c] = *(const float4*)&Kb[(size_t)(kt + j) * DH + c];
            *(float4*)&Vs[j][c] = *(const float4*)&Vb[(size_t)(kt + j) * DH + c];
        }
        __syncthreads();

        float sc[ABN];
        float tmax = mmax;
        #pragma unroll
        for (int j = 0; j < ABN; j++) {
            float a = 0.f;
            #pragma unroll
            for (int c = 0; c < 16; c++) {
                float4 kk = *(float4*)&Ks[j][c * 4];
                a = fmaf(q[c].x, kk.x, a);
                a = fmaf(q[c].y, kk.y, a);
                a = fmaf(q[c].z, kk.z, a);
                a = fmaf(q[c].w, kk.w, a);
            }
            sc[j] = a;
            tmax = fmaxf(tmax, a);
        }

        float alpha = __expf(mmax - tmax);
        lsum *= alpha;
        #pragma unroll
        for (int c = 0; c < 16; c++) {
            o[c].x *= alpha; o[c].y *= alpha; o[c].z *= alpha; o[c].w *= alpha;
        }
        mmax = tmax;

        #pragma unroll
        for (int j = 0; j < ABN; j++) {
            float p = __expf(sc[j] - mmax);
            lsum += p;
            #pragma unroll
            for (int c = 0; c < 16; c++) {
                float4 vv = *(float4*)&Vs[j][c * 4];
                o[c].x = fmaf(p, vv.x, o[c].x);
                o[c].y = fmaf(p, vv.y, o[c].y);
                o[c].z = fmaf(p, vv.z, o[c].z);
                o[c].w = fmaf(p, vv.w, o[c].w);
            }
        }
    }

    const float inv = 1.f / lsum;
    float* dst = &Ctx[((size_t)(b_ * SS + row)) * HH + h_ * DH];
    #pragma unroll
    for (int c = 0; c < 16; c++) {
        float4 r;
        r.x = o[c].x * inv; r.y = o[c].y * inv;
        r.z = o[c].z * inv; r.w = o[c].w * inv;
        *(float4*)&dst[c * 4] = r;
    }
}

// ---------------------------------------------------------------------------
extern "C" void kernel_launch(void* const* d_in, const int* in_sizes, int n_in,
                              void* d_out, int out_size)
{
    const float* key   = (const float*)d_in[0];
    const float* value = (const float*)d_in[1];
    const float* query = (const float*)d_in[2];
    const float* wq = (const float*)d_in[3];
    const float* bq = (const float*)d_in[4];
    const float* wk = (const float*)d_in[5];
    const float* bk = (const float*)d_in[6];
    const float* wv = (const float*)d_in[7];
    const float* bv = (const float*)d_in[8];
    const float* wo = (const float*)d_in[9];
    const float* bo = (const float*)d_in[10];
    float* out = (float*)d_out;

    float *q_p, *k_p, *v_p, *ctx_p;
    cudaGetSymbolAddress((void**)&q_p,   g_q);
    cudaGetSymbolAddress((void**)&k_p,   g_k);
    cudaGetSymbolAddress((void**)&v_p,   g_v);
    cudaGetSymbolAddress((void**)&ctx_p, g_ctx);

    dim3 gg(HH / BN, MTOT / BM);   // (16, 64)

    // QKV projections (Q pre-scaled by 1/sqrt(DH) = 1/8)
    gemm_k<<<gg, 256>>>(query, wq, bq, q_p, 0.125f, 1);
    gemm_k<<<gg, 256>>>(key,   wk, bk, k_p, 1.0f,   1);
    gemm_k<<<gg, 256>>>(value, wv, bv, v_p, 1.0f,   1);

    // Flash attention
    dim3 ga(SS / ABM, BB * NH);    // (16, 64)
    attn_k<<<ga, ABM>>>(q_p, k_p, v_p, ctx_p);

    // Output projection -> d_out
    gemm_k<<<gg, 256>>>(ctx_p, wo, bo, out, 1.0f, 0);
}

// round 4
// speedup vs baseline: 1.4718x; 1.4718x over previous
#include <cuda_runtime.h>
#include <cuda_bf16.h>
#include <cstdint>

typedef __nv_bfloat16 bf16;

#define BB 4
#define SS 2048
#define NHD 16
#define DH 64
#define HH 1024
#define MTOT (BB*SS)     // 8192
#define KP3 3072         // 3*1024 packed K
#define KPS 192          // 3*64   packed K (scores)
#define KPV 6144         // 3*2048 packed K (PV)

// ------------------------- scratch (device globals) -------------------------
__device__ bf16  g_Xp[(size_t)MTOT*KP3];        // 48 MB  packed A-side acts / ctx
__device__ bf16  g_Wt[(size_t)HH*KP3];          // 6 MB   packed B-side weight^T
__device__ bf16  g_Qp[(size_t)BB*NHD*SS*KPS];   // 48 MB
__device__ bf16  g_Kp[(size_t)BB*NHD*SS*KPS];   // 48 MB
__device__ bf16  g_Vt[(size_t)BB*NHD*DH*KPV];   // 48 MB
__device__ float g_S [(size_t)BB*NHD*SS*SS];    // 1 GiB  scores
__device__ bf16  g_Pp[(size_t)BB*NHD*SS*KPV];   // 1.5 GiB packed probs

// ------------------------- helpers -------------------------
__device__ __forceinline__ uint32_t s2u(const void* p) {
    uint32_t a;
    asm("{ .reg .u64 t; cvta.to.shared.u64 t, %1; cvt.u32.u64 %0, t; }" : "=r"(a) : "l"(p));
    return a;
}
#define CP_ASYNC16(dst, src) \
    asm volatile("cp.async.cg.shared.global [%0], [%1], 16;" :: "r"(dst), "l"(src))
#define CP_COMMIT() asm volatile("cp.async.commit_group;" ::: "memory")
#define CP_WAIT(n)  asm volatile("cp.async.wait_group %0;" :: "n"(n) : "memory")

__device__ __forceinline__ void ldm_x4(uint32_t* r, uint32_t addr) {
    asm volatile("ldmatrix.sync.aligned.m8n8.x4.shared.b16 {%0,%1,%2,%3}, [%4];"
        : "=r"(r[0]), "=r"(r[1]), "=r"(r[2]), "=r"(r[3]) : "r"(addr));
}
__device__ __forceinline__ void mma16816(float* d, const uint32_t* a, const uint32_t* b) {
    asm volatile("mma.sync.aligned.m16n8k16.row.col.f32.bf16.bf16.f32 "
        "{%0,%1,%2,%3}, {%4,%5,%6,%7}, {%8,%9}, {%0,%1,%2,%3};"
        : "+f"(d[0]), "+f"(d[1]), "+f"(d[2]), "+f"(d[3])
        : "r"(a[0]), "r"(a[1]), "r"(a[2]), "r"(a[3]), "r"(b[0]), "r"(b[1]));
}
__device__ __forceinline__ void split3(float f, bf16& hi, bf16& lo) {
    hi = __float2bfloat16(f);
    lo = __float2bfloat16(f - __bfloat162float(hi));
}

// ------------------------- pack kernels -------------------------
// A-side pack: X[M,1024] fp32 -> Xp[M, 3072] = [hi | lo | hi]
__global__ __launch_bounds__(256) void pack_a_k(const float* __restrict__ x,
                                                bf16* __restrict__ xp) {
    int i = blockIdx.x * 256 + threadIdx.x;      // one float4 per thread
    int row = i >> 8;
    int k4 = (i & 255) << 2;
    float4 f = *(const float4*)&x[((size_t)row << 10) + k4];
    float fv[4] = {f.x, f.y, f.z, f.w};
    bf16 h[4], l[4];
    #pragma unroll
    for (int q = 0; q < 4; q++) split3(fv[q], h[q], l[q]);
    size_t base = (size_t)row * KP3 + k4;
    *(__nv_bfloat162*)&xp[base]          = __nv_bfloat162(h[0], h[1]);
    *(__nv_bfloat162*)&xp[base + 2]      = __nv_bfloat162(h[2], h[3]);
    *(__nv_bfloat162*)&xp[base + 1024]   = __nv_bfloat162(l[0], l[1]);
    *(__nv_bfloat162*)&xp[base + 1026]   = __nv_bfloat162(l[2], l[3]);
    *(__nv_bfloat162*)&xp[base + 2048]   = __nv_bfloat162(h[0], h[1]);
    *(__nv_bfloat162*)&xp[base + 2050]   = __nv_bfloat162(h[2], h[3]);
}

// B-side pack + transpose: W[1024,1024] (k-major) -> Wt[n, 3072] = [hi | hi | lo]
__global__ __launch_bounds__(256) void pack_wt_k(const float* __restrict__ W,
                                                 bf16* __restrict__ Wt) {
    __shared__ float t[32][33];
    int tx = threadIdx.x & 31, ty = threadIdx.x >> 5;
    int n0 = blockIdx.x * 32, k0 = blockIdx.y * 32;
    #pragma unroll
    for (int r = 0; r < 4; r++) {
        int k = k0 + ty + r * 8;
        t[ty + r * 8][tx] = W[(size_t)k * HH + n0 + tx];
    }
    __syncthreads();
    #pragma unroll
    for (int r = 0; r < 4; r++) {
        int n = n0 + ty + r * 8;
        int k = k0 + tx;
        bf16 hi, lo; split3(t[tx][ty + r * 8], hi, lo);
        size_t base = (size_t)n * KP3 + k;
        Wt[base] = hi; Wt[base + 1024] = hi; Wt[base + 2048] = lo;
    }
}

// ------------------------- softmax + probs pack -------------------------
__global__ __launch_bounds__(256) void softmax_k(const float* __restrict__ S,
                                                 bf16* __restrict__ P) {
    __shared__ float redm[8], reds[8];
    size_t row = blockIdx.x;
    const float* r = S + row * SS;
    bf16* p = P + row * (size_t)KPV;
    int t = threadIdx.x, lane = t & 31, w = t >> 5;
    float v[8]; float m = -1e30f;
    #pragma unroll
    for (int i = 0; i < 8; i++) { v[i] = r[i * 256 + t]; m = fmaxf(m, v[i]); }
    #pragma unroll
    for (int o = 16; o > 0; o >>= 1) m = fmaxf(m, __shfl_xor_sync(0xffffffffu, m, o));
    if (lane == 0) redm[w] = m;
    __syncthreads();
    float mm = redm[0];
    #pragma unroll
    for (int i = 1; i < 8; i++) mm = fmaxf(mm, redm[i]);
    float s = 0.f;
    #pragma unroll
    for (int i = 0; i < 8; i++) { v[i] = __expf(v[i] - mm); s += v[i]; }
    #pragma unroll
    for (int o = 16; o > 0; o >>= 1) s += __shfl_xor_sync(0xffffffffu, s, o);
    if (lane == 0) reds[w] = s;
    __syncthreads();
    float tot = 0.f;
    #pragma unroll
    for (int i = 0; i < 8; i++) tot += reds[i];
    float inv = 1.f / tot;
    #pragma unroll
    for (int i = 0; i < 8; i++) {
        float pv = v[i] * inv;
        bf16 hi, lo; split3(pv, hi, lo);
        int c = i * 256 + t;
        p[c] = hi; p[2048 + c] = lo; p[4096 + c] = hi;   // A-side [hi|lo|hi]
    }
}

// ------------------------- mma.sync GEMM -------------------------
// D[M,N] = A[M,Kp] * B[N,Kp]^T  (both K-major packed bf16). CTA tile 128 x NT.
// 256 threads = 8 warps as 4x2; warp tile 32 x NT/2.
// EPI: 0 plain(+bias), 1 Qpack, 2 Kpack, 3 VTpack, 4 scores(fp32), 5 CTXpack
#define LDS 40   // padded bf16 elems per smem row (80B stride: conflict-free ldmatrix)

template<int NT, int EPI>
__global__ __launch_bounds__(256) void gemm_mma(
    const bf16* __restrict__ A, const bf16* __restrict__ B,
    float* __restrict__ outf, bf16* __restrict__ outb,
    const float* __restrict__ bias, float scale,
    int Kp, int lda, int ldb, size_t aBatch, size_t bBatch)
{
    extern __shared__ char smem[];
    const int tid = threadIdx.x, wid = tid >> 5, lane = tid & 31;
    const int m0 = blockIdx.y * 128, n0 = blockIdx.x * NT, z = blockIdx.z;

    constexpr int ABUF = 128 * LDS * 2;   // 10240 B
    constexpr int BBUF = NT * LDS * 2;
    const uint32_t sb = s2u(smem);
    const uint32_t uA[2] = { sb, sb + ABUF };
    const uint32_t uB[2] = { sb + 2 * ABUF, sb + 2 * ABUF + BBUF };

    const bf16* Ab = A + (size_t)z * aBatch + (size_t)m0 * lda;
    const bf16* Bb = B + (size_t)z * bBatch + (size_t)n0 * ldb;
    const int nC = Kp >> 5;   // K-chunks of 32

    auto loadChunk = [&](int c, int buf) {
        const bf16* ap = Ab + c * 32;
        #pragma unroll
        for (int p = 0; p < 2; p++) {
            int idx = tid + p * 256;
            int r = idx >> 2, sg = idx & 3;
            CP_ASYNC16(uA[buf] + r * (LDS * 2) + sg * 16,
                       (const char*)(ap + (size_t)r * lda) + sg * 16);
        }
        const bf16* bp = Bb + c * 32;
        #pragma unroll
        for (int p = 0; p < NT / 64; p++) {
            int idx = tid + p * 256;
            int r = idx >> 2, sg = idx & 3;
            CP_ASYNC16(uB[buf] + r * (LDS * 2) + sg * 16,
                       (const char*)(bp + (size_t)r * ldb) + sg * 16);
        }
        CP_COMMIT();
    };

    float acc[2][NT / 16][4];
    #pragma unroll
    for (int i = 0; i < 2; i++)
        #pragma unroll
        for (int j = 0; j < NT / 16; j++)
            #pragma unroll
            for (int q = 0; q < 4; q++) acc[i][j][q] = 0.f;

    const int wm = (wid & 3) * 32;
    const int wn = (wid >> 2) * (NT / 2);

    loadChunk(0, 0);
    for (int c = 0; c < nC; c++) {
        int buf = c & 1;
        if (c + 1 < nC) { loadChunk(c + 1, (c + 1) & 1); CP_WAIT(1); }
        else CP_WAIT(0);
        __syncthreads();
        #pragma unroll
        for (int ks = 0; ks < 2; ks++) {
            uint32_t a[2][4];
            #pragma unroll
            for (int im = 0; im < 2; im++) {
                uint32_t addr = uA[buf] +
                    ((wm + im * 16 + (lane & 15)) * LDS + ks * 16 + (lane >> 4) * 8) * 2;
                ldm_x4(a[im], addr);
            }
            uint32_t b[NT / 32][4];
            #pragma unroll
            for (int ig = 0; ig < NT / 32; ig++) {
                uint32_t addr = uB[buf] +
                    ((wn + ig * 16 + (lane & 7) + ((lane >> 4) << 3)) * LDS
                     + ks * 16 + (((lane >> 3) & 1) << 3)) * 2;
                ldm_x4(b[ig], addr);
            }
            #pragma unroll
            for (int im = 0; im < 2; im++)
                #pragma unroll
                for (int ig = 0; ig < NT / 32; ig++) {
                    mma16816(acc[im][ig * 2],     a[im], &b[ig][0]);
                    mma16816(acc[im][ig * 2 + 1], a[im], &b[ig][2]);
                }
        }
        __syncthreads();
    }

    // ------------------- epilogues -------------------
    if constexpr (EPI == 3) {
        // VT pack: stage fp32 tile in smem, then transpose-pack (NT == 128)
        float* stage = (float*)smem;
        #pragma unroll
        for (int im = 0; im < 2; im++)
            #pragma unroll
            for (int jn = 0; jn < NT / 16; jn++)
                #pragma unroll
                for (int h2 = 0; h2 < 2; h2++)
                    #pragma unroll
                    for (int cc = 0; cc < 2; cc++) {
                        int ml = wm + im * 16 + (lane >> 2) + h2 * 8;
                        int nl = wn + jn * 8 + (lane & 3) * 2 + cc;
                        stage[ml * 130 + nl] = acc[im][jn][h2 * 2 + cc] + bias[n0 + nl];
                    }
        __syncthreads();
        {
            const int bI = m0 >> 11, sBase = m0 & (SS - 1);
            int gl = tid >> 1;
            int gn = n0 + gl;
            int h = gn >> 6, d = gn & 63;
            size_t base = ((size_t)((bI * NHD + h) * DH + d)) * KPV;
            int s0 = (tid & 1) * 64;
            #pragma unroll 4
            for (int s = 0; s < 64; s++) {
                int sl = s0 + s;
                bf16 hi, lo; split3(stage[sl * 130 + gl], hi, lo);
                size_t sidx = base + sBase + sl;
                outb[sidx] = hi; outb[sidx + 2048] = hi; outb[sidx + 4096] = lo;
            }
        }
    } else {
        #pragma unroll
        for (int im = 0; im < 2; im++)
            #pragma unroll
            for (int jn = 0; jn < NT / 16; jn++)
                #pragma unroll
                for (int h2 = 0; h2 < 2; h2++)
                    #pragma unroll
                    for (int cc = 0; cc < 2; cc++) {
                        int m = m0 + wm + im * 16 + (lane >> 2) + h2 * 8;
                        int gn = n0 + wn + jn * 8 + (lane & 3) * 2 + cc;
                        float val = acc[im][jn][h2 * 2 + cc];
                        if constexpr (EPI == 0) {
                            outf[(size_t)m * HH + gn] = val + bias[gn];
                        } else if constexpr (EPI == 4) {
                            outf[(size_t)z * SS * SS + (size_t)m * SS + gn] = val;
                        } else if constexpr (EPI == 1 || EPI == 2) {
                            float v = (val + bias[gn]) * scale;
                            int h = gn >> 6, d = gn & 63;
                            int bI = m >> 11, sI = m & (SS - 1);
                            bf16 hi, lo; split3(v, hi, lo);
                            size_t base = ((size_t)(bI * NHD + h) * SS + sI) * KPS;
                            if constexpr (EPI == 1) {  // Q: A-side [hi|lo|hi]
                                outb[base + d] = hi; outb[base + 64 + d] = lo; outb[base + 128 + d] = hi;
                            } else {                   // K: B-side [hi|hi|lo]
                                outb[base + d] = hi; outb[base + 64 + d] = hi; outb[base + 128 + d] = lo;
                            }
                        } else {  // EPI == 5: ctx pack (A-side), z = bh
                            int b_ = z >> 4, h_ = z & 15;
                            bf16 hi, lo; split3(val, hi, lo);
                            size_t base = ((size_t)(b_ * SS + m)) * KP3 + h_ * DH + gn;
                            outb[base] = hi; outb[base + 1024] = lo; outb[base + 2048] = hi;
                        }
                    }
    }
}

// ------------------------- launch -------------------------
extern "C" void kernel_launch(void* const* d_in, const int* in_sizes, int n_in,
                              void* d_out, int out_size)
{
    const float* key   = (const float*)d_in[0];
    const float* value = (const float*)d_in[1];
    const float* query = (const float*)d_in[2];
    const float* wq = (const float*)d_in[3];
    const float* bq = (const float*)d_in[4];
    const float* wk = (const float*)d_in[5];
    const float* bk = (const float*)d_in[6];
    const float* wv = (const float*)d_in[7];
    const float* bv = (const float*)d_in[8];
    const float* wo = (const float*)d_in[9];
    const float* bo = (const float*)d_in[10];
    float* out = (float*)d_out;

    bf16 *xp, *wt, *qp, *kp, *vt, *pp; float* sc;
    cudaGetSymbolAddress((void**)&xp, g_Xp);
    cudaGetSymbolAddress((void**)&wt, g_Wt);
    cudaGetSymbolAddress((void**)&qp, g_Qp);
    cudaGetSymbolAddress((void**)&kp, g_Kp);
    cudaGetSymbolAddress((void**)&vt, g_Vt);
    cudaGetSymbolAddress((void**)&sc, g_S);
    cudaGetSymbolAddress((void**)&pp, g_Pp);

    constexpr int SM128  = 4 * 10240;            // 40960 (A+B double buffered)
    constexpr int SM64   = 2 * 10240 + 2 * 5120; // 30720
    constexpr int SMVT   = 128 * 130 * 4;        // 66560 (stage for EPI3)
    cudaFuncSetAttribute(gemm_mma<128,0>, cudaFuncAttributeMaxDynamicSharedMemorySize, SM128);
    cudaFuncSetAttribute(gemm_mma<128,1>, cudaFuncAttributeMaxDynamicSharedMemorySize, SM128);
    cudaFuncSetAttribute(gemm_mma<128,2>, cudaFuncAttributeMaxDynamicSharedMemorySize, SM128);
    cudaFuncSetAttribute(gemm_mma<128,3>, cudaFuncAttributeMaxDynamicSharedMemorySize, SMVT);
    cudaFuncSetAttribute(gemm_mma<128,4>, cudaFuncAttributeMaxDynamicSharedMemorySize, SM128);
    cudaFuncSetAttribute(gemm_mma<64,5>,  cudaFuncAttributeMaxDynamicSharedMemorySize, SM64);

    dim3 gw(32, 32);
    dim3 gproj(HH / 128, MTOT / 128, 1);        // (8, 64)
    const size_t zero = 0;

    // Q projection (scale 1/8 folded in)
    pack_wt_k<<<gw, 256>>>(wq, wt);
    pack_a_k<<<MTOT * HH / 1024, 256>>>(query, xp);
    gemm_mma<128,1><<<gproj, 256, SM128>>>(xp, wt, nullptr, qp, bq, 0.125f, KP3, KP3, KP3, zero, zero);
    // K projection
    pack_wt_k<<<gw, 256>>>(wk, wt);
    pack_a_k<<<MTOT * HH / 1024, 256>>>(key, xp);
    gemm_mma<128,2><<<gproj, 256, SM128>>>(xp, wt, nullptr, kp, bk, 1.0f, KP3, KP3, KP3, zero, zero);
    // V projection (transposed pack)
    pack_wt_k<<<gw, 256>>>(wv, wt);
    pack_a_k<<<MTOT * HH / 1024, 256>>>(value, xp);
    gemm_mma<128,3><<<gproj, 256, SMVT>>>(xp, wt, nullptr, vt, bv, 1.0f, KP3, KP3, KP3, zero, zero);

    // scores: per bh, S[2048,2048] = Qp * Kp^T
    dim3 gsc(SS / 128, SS / 128, BB * NHD);     // (16, 16, 64)
    gemm_mma<128,4><<<gsc, 256, SM128>>>(qp, kp, sc, nullptr, nullptr, 1.0f,
                                         KPS, KPS, KPS, (size_t)SS * KPS, (size_t)SS * KPS);
    // softmax + probs pack
    softmax_k<<<BB * NHD * SS, 256>>>(sc, pp);

    // PV: per bh, ctx[2048,64] = Pp * Vt^T -> packed ctx into g_Xp
    dim3 gpv(1, SS / 128, BB * NHD);            // (1, 16, 64)
    gemm_mma<64,5><<<gpv, 256, SM64>>>(pp, vt, nullptr, xp, nullptr, 1.0f,
                                       KPV, KPV, KPV, (size_t)SS * KPV, (size_t)DH * KPV);

    // output projection
    pack_wt_k<<<gw, 256>>>(wo, wt);
    gemm_mma<128,0><<<gproj, 256, SM128>>>(xp, wt, out, nullptr, bo, 1.0f, KP3, KP3, KP3, zero, zero);
}

// round 5
// speedup vs baseline: 2.2641x; 1.5384x over previous
#include <cuda_runtime.h>
#include <cuda_bf16.h>
#include <cstdint>

typedef __nv_bfloat16 bf16;

#define BB 4
#define SS 2048
#define NHD 16
#define DH 64
#define HH 1024
#define MTOT (BB*SS)     // 8192
#define KP3 3072         // 3*1024 packed K (projections)
#define KPS 192          // 3*64   packed K (QK)
#define KPV2 4096        // 2*2048 packed V (hi | lo)

// ------------------------- scratch (device globals) -------------------------
__device__ bf16  g_Xp[(size_t)MTOT*KP3];        // 48 MB  packed acts / packed ctx
__device__ bf16  g_Wt[(size_t)HH*KP3];          // 6 MB   packed weight^T
__device__ bf16  g_Qp[(size_t)BB*NHD*SS*KPS];   // 48 MB
__device__ bf16  g_Kp[(size_t)BB*NHD*SS*KPS];   // 48 MB
__device__ bf16  g_Vt[(size_t)BB*NHD*DH*KPV2];  // 32 MB  [bh][dh][hi 2048 | lo 2048]

// ------------------------- helpers -------------------------
__device__ __forceinline__ uint32_t s2u(const void* p) {
    uint32_t a;
    asm("{ .reg .u64 t; cvta.to.shared.u64 t, %1; cvt.u32.u64 %0, t; }" : "=r"(a) : "l"(p));
    return a;
}
#define CP_ASYNC16(dst, src) \
    asm volatile("cp.async.cg.shared.global [%0], [%1], 16;" :: "r"(dst), "l"(src))
#define CP_COMMIT() asm volatile("cp.async.commit_group;" ::: "memory")
#define CP_WAIT(n)  asm volatile("cp.async.wait_group %0;" :: "n"(n) : "memory")

__device__ __forceinline__ void ldm_x4(uint32_t* r, uint32_t addr) {
    asm volatile("ldmatrix.sync.aligned.m8n8.x4.shared.b16 {%0,%1,%2,%3}, [%4];"
        : "=r"(r[0]), "=r"(r[1]), "=r"(r[2]), "=r"(r[3]) : "r"(addr));
}
__device__ __forceinline__ void mma16816(float* d, const uint32_t* a, const uint32_t* b) {
    asm volatile("mma.sync.aligned.m16n8k16.row.col.f32.bf16.bf16.f32 "
        "{%0,%1,%2,%3}, {%4,%5,%6,%7}, {%8,%9}, {%0,%1,%2,%3};"
        : "+f"(d[0]), "+f"(d[1]), "+f"(d[2]), "+f"(d[3])
        : "r"(a[0]), "r"(a[1]), "r"(a[2]), "r"(a[3]), "r"(b[0]), "r"(b[1]));
}
__device__ __forceinline__ void split3(float f, bf16& hi, bf16& lo) {
    hi = __float2bfloat16(f);
    lo = __float2bfloat16(f - __bfloat162float(hi));
}
__device__ __forceinline__ uint32_t pk2(float lo, float hi) {   // low=lo elem
    uint32_t r;
    asm("cvt.rn.bf16x2.f32 %0, %1, %2;" : "=r"(r) : "f"(hi), "f"(lo));
    return r;
}

// ------------------------- pack kernels -------------------------
// A-side pack: X[M,1024] fp32 -> Xp[M, 3072] = [hi | lo | hi]
__global__ __launch_bounds__(256) void pack_a_k(const float* __restrict__ x,
                                                bf16* __restrict__ xp) {
    int i = blockIdx.x * 256 + threadIdx.x;
    int row = i >> 8;
    int k4 = (i & 255) << 2;
    float4 f = *(const float4*)&x[((size_t)row << 10) + k4];
    float fv[4] = {f.x, f.y, f.z, f.w};
    bf16 h[4], l[4];
    #pragma unroll
    for (int q = 0; q < 4; q++) split3(fv[q], h[q], l[q]);
    size_t base = (size_t)row * KP3 + k4;
    *(__nv_bfloat162*)&xp[base]          = __nv_bfloat162(h[0], h[1]);
    *(__nv_bfloat162*)&xp[base + 2]      = __nv_bfloat162(h[2], h[3]);
    *(__nv_bfloat162*)&xp[base + 1024]   = __nv_bfloat162(l[0], l[1]);
    *(__nv_bfloat162*)&xp[base + 1026]   = __nv_bfloat162(l[2], l[3]);
    *(__nv_bfloat162*)&xp[base + 2048]   = __nv_bfloat162(h[0], h[1]);
    *(__nv_bfloat162*)&xp[base + 2050]   = __nv_bfloat162(h[2], h[3]);
}

// B-side pack + transpose: W[1024,1024] -> Wt[n, 3072] = [hi | hi | lo]
__global__ __launch_bounds__(256) void pack_wt_k(const float* __restrict__ W,
                                                 bf16* __restrict__ Wt) {
    __shared__ float t[32][33];
    int tx = threadIdx.x & 31, ty = threadIdx.x >> 5;
    int n0 = blockIdx.x * 32, k0 = blockIdx.y * 32;
    #pragma unroll
    for (int r = 0; r < 4; r++) {
        int k = k0 + ty + r * 8;
        t[ty + r * 8][tx] = W[(size_t)k * HH + n0 + tx];
    }
    __syncthreads();
    #pragma unroll
    for (int r = 0; r < 4; r++) {
        int n = n0 + ty + r * 8;
        int k = k0 + tx;
        bf16 hi, lo; split3(t[tx][ty + r * 8], hi, lo);
        size_t base = (size_t)n * KP3 + k;
        Wt[base] = hi; Wt[base + 1024] = hi; Wt[base + 2048] = lo;
    }
}

// ------------------------- mma.sync GEMM (projections) -------------------------
// EPI: 0 plain(+bias), 1 Qpack, 2 Kpack, 3 VTpack(2-section)
#define LDS 40

template<int NT, int EPI>
__global__ __launch_bounds__(256) void gemm_mma(
    const bf16* __restrict__ A, const bf16* __restrict__ B,
    float* __restrict__ outf, bf16* __restrict__ outb,
    const float* __restrict__ bias, float scale,
    int Kp, int lda, int ldb)
{
    extern __shared__ char smem[];
    const int tid = threadIdx.x, wid = tid >> 5, lane = tid & 31;
    const int m0 = blockIdx.y * 128, n0 = blockIdx.x * NT;

    constexpr int ABUF = 128 * LDS * 2;
    constexpr int BBUF = NT * LDS * 2;
    const uint32_t sb = s2u(smem);
    const uint32_t uA[2] = { sb, sb + ABUF };
    const uint32_t uB[2] = { sb + 2 * ABUF, sb + 2 * ABUF + BBUF };

    const bf16* Ab = A + (size_t)m0 * lda;
    const bf16* Bb = B + (size_t)n0 * ldb;
    const int nC = Kp >> 5;

    auto loadChunk = [&](int c, int buf) {
        const bf16* ap = Ab + c * 32;
        #pragma unroll
        for (int p = 0; p < 2; p++) {
            int idx = tid + p * 256;
            int r = idx >> 2, sg = idx & 3;
            CP_ASYNC16(uA[buf] + r * (LDS * 2) + sg * 16,
                       (const char*)(ap + (size_t)r * lda) + sg * 16);
        }
        const bf16* bp = Bb + c * 32;
        #pragma unroll
        for (int p = 0; p < NT / 64; p++) {
            int idx = tid + p * 256;
            int r = idx >> 2, sg = idx & 3;
            CP_ASYNC16(uB[buf] + r * (LDS * 2) + sg * 16,
                       (const char*)(bp + (size_t)r * ldb) + sg * 16);
        }
        CP_COMMIT();
    };

    float acc[2][NT / 16][4];
    #pragma unroll
    for (int i = 0; i < 2; i++)
        #pragma unroll
        for (int j = 0; j < NT / 16; j++)
            #pragma unroll
            for (int q = 0; q < 4; q++) acc[i][j][q] = 0.f;

    const int wm = (wid & 3) * 32;
    const int wn = (wid >> 2) * (NT / 2);

    loadChunk(0, 0);
    for (int c = 0; c < nC; c++) {
        int buf = c & 1;
        if (c + 1 < nC) { loadChunk(c + 1, (c + 1) & 1); CP_WAIT(1); }
        else CP_WAIT(0);
        __syncthreads();
        #pragma unroll
        for (int ks = 0; ks < 2; ks++) {
            uint32_t a[2][4];
            #pragma unroll
            for (int im = 0; im < 2; im++) {
                uint32_t addr = uA[buf] +
                    ((wm + im * 16 + (lane & 15)) * LDS + ks * 16 + (lane >> 4) * 8) * 2;
                ldm_x4(a[im], addr);
            }
            uint32_t b[NT / 32][4];
            #pragma unroll
            for (int ig = 0; ig < NT / 32; ig++) {
                uint32_t addr = uB[buf] +
                    ((wn + ig * 16 + (lane & 7) + ((lane >> 4) << 3)) * LDS
                     + ks * 16 + (((lane >> 3) & 1) << 3)) * 2;
                ldm_x4(b[ig], addr);
            }
            #pragma unroll
            for (int im = 0; im < 2; im++)
                #pragma unroll
                for (int ig = 0; ig < NT / 32; ig++) {
                    mma16816(acc[im][ig * 2],     a[im], &b[ig][0]);
                    mma16816(acc[im][ig * 2 + 1], a[im], &b[ig][2]);
                }
        }
        __syncthreads();
    }

    if constexpr (EPI == 3) {
        float* stage = (float*)smem;
        #pragma unroll
        for (int im = 0; im < 2; im++)
            #pragma unroll
            for (int jn = 0; jn < NT / 16; jn++)
                #pragma unroll
                for (int h2 = 0; h2 < 2; h2++)
                    #pragma unroll
                    for (int cc = 0; cc < 2; cc++) {
                        int ml = wm + im * 16 + (lane >> 2) + h2 * 8;
                        int nl = wn + jn * 8 + (lane & 3) * 2 + cc;
                        stage[ml * 130 + nl] = acc[im][jn][h2 * 2 + cc] + bias[n0 + nl];
                    }
        __syncthreads();
        {
            const int bI = m0 >> 11, sBase = m0 & (SS - 1);
            int gl = tid >> 1;
            int gn = n0 + gl;
            int h = gn >> 6, d = gn & 63;
            size_t base = ((size_t)((bI * NHD + h) * DH + d)) * KPV2;
            int s0 = (tid & 1) * 64;
            #pragma unroll 4
            for (int s = 0; s < 64; s++) {
                int sl = s0 + s;
                bf16 hi, lo; split3(stage[sl * 130 + gl], hi, lo);
                size_t sidx = base + sBase + sl;
                outb[sidx] = hi; outb[sidx + 2048] = lo;
            }
        }
    } else {
        #pragma unroll
        for (int im = 0; im < 2; im++)
            #pragma unroll
            for (int jn = 0; jn < NT / 16; jn++)
                #pragma unroll
                for (int h2 = 0; h2 < 2; h2++)
                    #pragma unroll
                    for (int cc = 0; cc < 2; cc++) {
                        int m = m0 + wm + im * 16 + (lane >> 2) + h2 * 8;
                        int gn = n0 + wn + jn * 8 + (lane & 3) * 2 + cc;
                        float val = acc[im][jn][h2 * 2 + cc];
                        if constexpr (EPI == 0) {
                            outf[(size_t)m * HH + gn] = val + bias[gn];
                        } else {
                            float v = (val + bias[gn]) * scale;
                            int h = gn >> 6, d = gn & 63;
                            int bI = m >> 11, sI = m & (SS - 1);
                            bf16 hi, lo; split3(v, hi, lo);
                            size_t base = ((size_t)(bI * NHD + h) * SS + sI) * KPS;
                            if constexpr (EPI == 1) {  // Q: A-side [hi|lo|hi]
                                outb[base + d] = hi; outb[base + 64 + d] = lo; outb[base + 128 + d] = hi;
                            } else {                   // K: B-side [hi|hi|lo]
                                outb[base + d] = hi; outb[base + 64 + d] = hi; outb[base + 128 + d] = lo;
                            }
                        }
                    }
    }
}

// ------------------------- fused flash attention -------------------------
// grid (16 q-tiles, 64 bh), 256 thr = 8 warps x 16 query rows.
// Qp [hi|lo|hi], Kp [hi|hi|lo] (k=192); V 2-section; 3-chain PV.
#define KSTR 200   // smem row stride (elems) for Q/K tile: 400B, conflict-free
#define VSTR 136   // 272B, conflict-free

__global__ __launch_bounds__(256, 1) void flash_k(
    const bf16* __restrict__ Qp, const bf16* __restrict__ Kp,
    const bf16* __restrict__ Vt, bf16* __restrict__ Ctx)
{
    extern __shared__ char smem[];
    const int tid = threadIdx.x, wid = tid >> 5, lane = tid & 31;
    const int qt = blockIdx.x, bh = blockIdx.y;
    const int b_ = bh >> 4, h_ = bh & 15;
    const uint32_t sb = s2u(smem);
    const uint32_t uK  = sb;                       // 128*KSTR*2 = 51200
    const uint32_t uVh = sb + 128 * KSTR * 2;      // 64*VSTR*2 = 17408
    const uint32_t uVl = uVh + 64 * VSTR * 2;

    const bf16* Qb = Qp + ((size_t)bh * SS + qt * 128) * KPS;
    const bf16* Kb = Kp + (size_t)bh * SS * KPS;
    const bf16* Vb = Vt + (size_t)bh * DH * KPV2;

    // stage Q through uK, pull A-fragments to registers
    #pragma unroll
    for (int p = 0; p < 12; p++) {
        int idx = tid + p * 256;
        int r = idx / 24, sg = idx % 24;
        CP_ASYNC16(uK + r * (KSTR * 2) + sg * 16,
                   (const char*)(Qb + (size_t)r * KPS) + sg * 16);
    }
    CP_COMMIT(); CP_WAIT(0); __syncthreads();

    uint32_t qf[12][4];
    {
        int rbase = wid * 16 + (lane & 15);
        #pragma unroll
        for (int kc = 0; kc < 12; kc++)
            ldm_x4(qf[kc], uK + (rbase * KSTR + kc * 16 + (lane >> 4) * 8) * 2);
    }
    __syncthreads();

    float oacc[8][4];
    #pragma unroll
    for (int j = 0; j < 8; j++)
        #pragma unroll
        for (int q = 0; q < 4; q++) oacc[j][q] = 0.f;
    float M0 = -1e30f, M1 = -1e30f, L0 = 0.f, L1 = 0.f;

    for (int kt = 0; kt < SS; kt += 128) {
        // K tile (group A), V tiles (group B)
        const bf16* kp2 = Kb + (size_t)kt * KPS;
        #pragma unroll
        for (int p = 0; p < 12; p++) {
            int idx = tid + p * 256;
            int r = idx / 24, sg = idx % 24;
            CP_ASYNC16(uK + r * (KSTR * 2) + sg * 16,
                       (const char*)(kp2 + (size_t)r * KPS) + sg * 16);
        }
        CP_COMMIT();
        #pragma unroll
        for (int p = 0; p < 4; p++) {
            int idx = tid + p * 256;
            int r = idx >> 4, sg = idx & 15;
            const char* s = (const char*)(Vb + (size_t)r * KPV2 + kt) + sg * 16;
            CP_ASYNC16(uVh + r * (VSTR * 2) + sg * 16, s);
            CP_ASYNC16(uVl + r * (VSTR * 2) + sg * 16, s + 4096);
        }
        CP_COMMIT();
        CP_WAIT(1);              // K ready; V still in flight
        __syncthreads();

        // S = Q K^T  (16 rows x 128 keys per warp)
        float sc[16][4];
        #pragma unroll
        for (int t = 0; t < 16; t++)
            #pragma unroll
            for (int q = 0; q < 4; q++) sc[t][q] = 0.f;
        #pragma unroll
        for (int kc = 0; kc < 12; kc++) {
            #pragma unroll
            for (int kg = 0; kg < 8; kg++) {
                uint32_t b[4];
                uint32_t addr = uK + ((kg * 16 + (lane & 7) + ((lane >> 4) << 3)) * KSTR
                                      + kc * 16 + (((lane >> 3) & 1) << 3)) * 2;
                ldm_x4(b, addr);
                mma16816(sc[kg * 2],     qf[kc], b);
                mma16816(sc[kg * 2 + 1], qf[kc], b + 2);
            }
        }

        // online softmax (rows r = lane>>2 and r+8; quad-reduce over lanes^1,^2)
        float m0 = -1e30f, m1 = -1e30f;
        #pragma unroll
        for (int t = 0; t < 16; t++) {
            m0 = fmaxf(m0, fmaxf(sc[t][0], sc[t][1]));
            m1 = fmaxf(m1, fmaxf(sc[t][2], sc[t][3]));
        }
        #pragma unroll
        for (int off = 1; off <= 2; off <<= 1) {
            m0 = fmaxf(m0, __shfl_xor_sync(0xffffffffu, m0, off));
            m1 = fmaxf(m1, __shfl_xor_sync(0xffffffffu, m1, off));
        }
        float nM0 = fmaxf(M0, m0), nM1 = fmaxf(M1, m1);
        float a0 = __expf(M0 - nM0), a1 = __expf(M1 - nM1);
        M0 = nM0; M1 = nM1;
        float s0 = 0.f, s1 = 0.f;
        #pragma unroll
        for (int t = 0; t < 16; t++) {
            sc[t][0] = __expf(sc[t][0] - M0); s0 += sc[t][0];
            sc[t][1] = __expf(sc[t][1] - M0); s0 += sc[t][1];
            sc[t][2] = __expf(sc[t][2] - M1); s1 += sc[t][2];
            sc[t][3] = __expf(sc[t][3] - M1); s1 += sc[t][3];
        }
        #pragma unroll
        for (int off = 1; off <= 2; off <<= 1) {
            s0 += __shfl_xor_sync(0xffffffffu, s0, off);
            s1 += __shfl_xor_sync(0xffffffffu, s1, off);
        }
        L0 = L0 * a0 + s0; L1 = L1 * a1 + s1;
        #pragma unroll
        for (int j = 0; j < 8; j++) {
            oacc[j][0] *= a0; oacc[j][1] *= a0;
            oacc[j][2] *= a1; oacc[j][3] *= a1;
        }

        CP_WAIT(0);              // V ready
        __syncthreads();

        // PV: 3 chains  (Phi*Vhi + Plo*Vhi + Phi*Vlo)
        #pragma unroll
        for (int j = 0; j < 8; j++) {
            // C->A conversion with hi/lo split
            uint32_t ph[4], pl[4];
            float c00 = sc[2*j][0],   c01 = sc[2*j][1];
            float c02 = sc[2*j][2],   c03 = sc[2*j][3];
            float c10 = sc[2*j+1][0], c11 = sc[2*j+1][1];
            float c12 = sc[2*j+1][2], c13 = sc[2*j+1][3];
            float h00 = __bfloat162float(__float2bfloat16(c00));
            float h01 = __bfloat162float(__float2bfloat16(c01));
            float h02 = __bfloat162float(__float2bfloat16(c02));
            float h03 = __bfloat162float(__float2bfloat16(c03));
            float h10 = __bfloat162float(__float2bfloat16(c10));
            float h11 = __bfloat162float(__float2bfloat16(c11));
            float h12 = __bfloat162float(__float2bfloat16(c12));
            float h13 = __bfloat162float(__float2bfloat16(c13));
            ph[0] = pk2(h00, h01); ph[1] = pk2(h02, h03);
            ph[2] = pk2(h10, h11); ph[3] = pk2(h12, h13);
            pl[0] = pk2(c00 - h00, c01 - h01); pl[1] = pk2(c02 - h02, c03 - h03);
            pl[2] = pk2(c10 - h10, c11 - h11); pl[3] = pk2(c12 - h12, c13 - h13);

            uint32_t koff = (j * 16 + (((lane >> 3) & 1) << 3)) * 2;
            uint32_t rsel = (lane & 7) + ((lane >> 4) << 3);
            #pragma unroll
            for (int dg = 0; dg < 4; dg++) {
                uint32_t row = dg * 16 + rsel;
                uint32_t bh4[4], bl4[4];
                ldm_x4(bh4, uVh + row * (VSTR * 2) + koff);
                ldm_x4(bl4, uVl + row * (VSTR * 2) + koff);
                mma16816(oacc[dg * 2],     ph, bh4);
                mma16816(oacc[dg * 2 + 1], ph, bh4 + 2);
                mma16816(oacc[dg * 2],     pl, bh4);
                mma16816(oacc[dg * 2 + 1], pl, bh4 + 2);
                mma16816(oacc[dg * 2],     ph, bl4);
                mma16816(oacc[dg * 2 + 1], ph, bl4 + 2);
            }
        }
        __syncthreads();
    }

    // epilogue: normalize + packed ctx write [hi|lo|hi]
    float i0 = 1.f / L0, i1 = 1.f / L1;
    int r = lane >> 2;
    int q0 = qt * 128 + wid * 16;
    size_t row0 = ((size_t)(b_ * SS + q0 + r)) * KP3;
    size_t row1 = ((size_t)(b_ * SS + q0 + r + 8)) * KP3;
    int cbase = h_ * DH + (lane & 3) * 2;
    #pragma unroll
    for (int t = 0; t < 8; t++) {
        int col = cbase + t * 8;
        float v0 = oacc[t][0] * i0, v1 = oacc[t][1] * i0;
        float w0 = oacc[t][2] * i1, w1 = oacc[t][3] * i1;
        float vh0 = __bfloat162float(__float2bfloat16(v0));
        float vh1 = __bfloat162float(__float2bfloat16(v1));
        float wh0 = __bfloat162float(__float2bfloat16(w0));
        float wh1 = __bfloat162float(__float2bfloat16(w1));
        *(uint32_t*)&Ctx[row0 + col]        = pk2(vh0, vh1);
        *(uint32_t*)&Ctx[row0 + 1024 + col] = pk2(v0 - vh0, v1 - vh1);
        *(uint32_t*)&Ctx[row0 + 2048 + col] = pk2(vh0, vh1);
        *(uint32_t*)&Ctx[row1 + col]        = pk2(wh0, wh1);
        *(uint32_t*)&Ctx[row1 + 1024 + col] = pk2(w0 - wh0, w1 - wh1);
        *(uint32_t*)&Ctx[row1 + 2048 + col] = pk2(wh0, wh1);
    }
}

// ------------------------- launch -------------------------
extern "C" void kernel_launch(void* const* d_in, const int* in_sizes, int n_in,
                              void* d_out, int out_size)
{
    const float* key   = (const float*)d_in[0];
    const float* value = (const float*)d_in[1];
    const float* query = (const float*)d_in[2];
    const float* wq = (const float*)d_in[3];
    const float* bq = (const float*)d_in[4];
    const float* wk = (const float*)d_in[5];
    const float* bk = (const float*)d_in[6];
    const float* wv = (const float*)d_in[7];
    const float* bv = (const float*)d_in[8];
    const float* wo = (const float*)d_in[9];
    const float* bo = (const float*)d_in[10];
    float* out = (float*)d_out;

    bf16 *xp, *wt, *qp, *kp, *vt;
    cudaGetSymbolAddress((void**)&xp, g_Xp);
    cudaGetSymbolAddress((void**)&wt, g_Wt);
    cudaGetSymbolAddress((void**)&qp, g_Qp);
    cudaGetSymbolAddress((void**)&kp, g_Kp);
    cudaGetSymbolAddress((void**)&vt, g_Vt);

    constexpr int SM128 = 4 * 10240;        // 40960
    constexpr int SMVT  = 128 * 130 * 4;    // 66560
    constexpr int SMFL  = 128 * KSTR * 2 + 2 * 64 * VSTR * 2;  // 86016
    cudaFuncSetAttribute(gemm_mma<128,0>, cudaFuncAttributeMaxDynamicSharedMemorySize, SM128);
    cudaFuncSetAttribute(gemm_mma<128,1>, cudaFuncAttributeMaxDynamicSharedMemorySize, SM128);
    cudaFuncSetAttribute(gemm_mma<128,2>, cudaFuncAttributeMaxDynamicSharedMemorySize, SM128);
    cudaFuncSetAttribute(gemm_mma<128,3>, cudaFuncAttributeMaxDynamicSharedMemorySize, SMVT);
    cudaFuncSetAttribute(flash_k, cudaFuncAttributeMaxDynamicSharedMemorySize, SMFL);

    dim3 gw(32, 32);
    dim3 gproj(HH / 128, MTOT / 128, 1);

    // Q projection (1/sqrt(DH) folded)
    pack_wt_k<<<gw, 256>>>(wq, wt);
    pack_a_k<<<MTOT * HH / 1024, 256>>>(query, xp);
    gemm_mma<128,1><<<gproj, 256, SM128>>>(xp, wt, nullptr, qp, bq, 0.125f, KP3, KP3, KP3);
    // K projection
    pack_wt_k<<<gw, 256>>>(wk, wt);
    pack_a_k<<<MTOT * HH / 1024, 256>>>(key, xp);
    gemm_mma<128,2><<<gproj, 256, SM128>>>(xp, wt, nullptr, kp, bk, 1.0f, KP3, KP3, KP3);
    // V projection (2-section transposed pack)
    pack_wt_k<<<gw, 256>>>(wv, wt);
    pack_a_k<<<MTOT * HH / 1024, 256>>>(value, xp);
    gemm_mma<128,3><<<gproj, 256, SMVT>>>(xp, wt, nullptr, vt, bv, 1.0f, KP3, KP3, KP3);

    // fused attention -> packed ctx in g_Xp
    dim3 gf(SS / 128, BB * NHD);
    flash_k<<<gf, 256, SMFL>>>(qp, kp, vt, xp);

    // output projection
    pack_wt_k<<<gw, 256>>>(wo, wt);
    gemm_mma<128,0><<<gproj, 256, SM128>>>(xp, wt, out, nullptr, bo, 1.0f, KP3, KP3, KP3);
}

// round 6
// speedup vs baseline: 2.4148x; 1.0665x over previous
#include <cuda_runtime.h>
#include <cuda_bf16.h>
#include <cstdint>

typedef __nv_bfloat16 bf16;

#define BB 4
#define SS 2048
#define NHD 16
#define DH 64
#define HH 1024
#define MTOT (BB*SS)     // 8192
#define KP3 3072         // 3*1024 packed K (projections)
#define KPS 192          // 3*64   packed K (QK)
#define KPV2 4096        // 2*2048 packed V (hi | lo)

#define ASLAB ((size_t)MTOT*KP3)
#define WSLAB ((size_t)HH*KP3)

// ------------------------- scratch (device globals) -------------------------
__device__ bf16  g_Xp[3*ASLAB];                 // 151 MB packed acts (q,k,v) / ctx in slab0
__device__ bf16  g_Wt[4*WSLAB];                 // 25 MB  packed weights^T
__device__ bf16  g_Qp[(size_t)BB*NHD*SS*KPS];   // 48 MB
__device__ bf16  g_Kp[(size_t)BB*NHD*SS*KPS];   // 48 MB
__device__ bf16  g_Vt[(size_t)BB*NHD*DH*KPV2];  // 32 MB

// ------------------------- helpers -------------------------
__device__ __forceinline__ uint32_t s2u(const void* p) {
    uint32_t a;
    asm("{ .reg .u64 t; cvta.to.shared.u64 t, %1; cvt.u32.u64 %0, t; }" : "=r"(a) : "l"(p));
    return a;
}
#define CP_ASYNC16(dst, src) \
    asm volatile("cp.async.cg.shared.global [%0], [%1], 16;" :: "r"(dst), "l"(src))
#define CP_COMMIT() asm volatile("cp.async.commit_group;" ::: "memory")
#define CP_WAIT(n)  asm volatile("cp.async.wait_group %0;" :: "n"(n) : "memory")

__device__ __forceinline__ void ldm_x4(uint32_t* r, uint32_t addr) {
    asm volatile("ldmatrix.sync.aligned.m8n8.x4.shared.b16 {%0,%1,%2,%3}, [%4];"
        : "=r"(r[0]), "=r"(r[1]), "=r"(r[2]), "=r"(r[3]) : "r"(addr));
}
__device__ __forceinline__ void mma16816(float* d, const uint32_t* a, const uint32_t* b) {
    asm volatile("mma.sync.aligned.m16n8k16.row.col.f32.bf16.bf16.f32 "
        "{%0,%1,%2,%3}, {%4,%5,%6,%7}, {%8,%9}, {%0,%1,%2,%3};"
        : "+f"(d[0]), "+f"(d[1]), "+f"(d[2]), "+f"(d[3])
        : "r"(a[0]), "r"(a[1]), "r"(a[2]), "r"(a[3]), "r"(b[0]), "r"(b[1]));
}
__device__ __forceinline__ void split3(float f, bf16& hi, bf16& lo) {
    hi = __float2bfloat16(f);
    lo = __float2bfloat16(f - __bfloat162float(hi));
}
__device__ __forceinline__ uint32_t pk2(float lo, float hi) {
    uint32_t r;
    asm("cvt.rn.bf16x2.f32 %0, %1, %2;" : "=r"(r) : "f"(hi), "f"(lo));
    return r;
}

// ------------------------- pack kernels (merged) -------------------------
// A-side pack: X[M,1024] fp32 -> Xp[M, 3072] = [hi | lo | hi]; z selects input
__global__ __launch_bounds__(256) void pack_a_k(
    const float* __restrict__ q, const float* __restrict__ k,
    const float* __restrict__ v, bf16* __restrict__ xpBase)
{
    int z = blockIdx.y;
    const float* x = (z == 0) ? q : (z == 1) ? k : v;
    bf16* xp = xpBase + (size_t)z * ASLAB;
    int i = blockIdx.x * 256 + threadIdx.x;
    int row = i >> 8;
    int k4 = (i & 255) << 2;
    float4 f = *(const float4*)&x[((size_t)row << 10) + k4];
    float fv[4] = {f.x, f.y, f.z, f.w};
    bf16 h[4], l[4];
    #pragma unroll
    for (int qq = 0; qq < 4; qq++) split3(fv[qq], h[qq], l[qq]);
    size_t base = (size_t)row * KP3 + k4;
    *(__nv_bfloat162*)&xp[base]        = __nv_bfloat162(h[0], h[1]);
    *(__nv_bfloat162*)&xp[base + 2]    = __nv_bfloat162(h[2], h[3]);
    *(__nv_bfloat162*)&xp[base + 1024] = __nv_bfloat162(l[0], l[1]);
    *(__nv_bfloat162*)&xp[base + 1026] = __nv_bfloat162(l[2], l[3]);
    *(__nv_bfloat162*)&xp[base + 2048] = __nv_bfloat162(h[0], h[1]);
    *(__nv_bfloat162*)&xp[base + 2050] = __nv_bfloat162(h[2], h[3]);
}

// B-side pack+transpose: W -> Wt[n,3072]=[hi|hi|lo]; z selects weight
__global__ __launch_bounds__(256) void pack_wt_k(
    const float* __restrict__ wq, const float* __restrict__ wk,
    const float* __restrict__ wv, const float* __restrict__ wo,
    bf16* __restrict__ wtBase)
{
    __shared__ float t[32][33];
    int z = blockIdx.z;
    const float* W = (z == 0) ? wq : (z == 1) ? wk : (z == 2) ? wv : wo;
    bf16* Wt = wtBase + (size_t)z * WSLAB;
    int tx = threadIdx.x & 31, ty = threadIdx.x >> 5;
    int n0 = blockIdx.x * 32, k0 = blockIdx.y * 32;
    #pragma unroll
    for (int r = 0; r < 4; r++) {
        int k = k0 + ty + r * 8;
        t[ty + r * 8][tx] = W[(size_t)k * HH + n0 + tx];
    }
    __syncthreads();
    #pragma unroll
    for (int r = 0; r < 4; r++) {
        int n = n0 + ty + r * 8;
        int k = k0 + tx;
        bf16 hi, lo; split3(t[tx][ty + r * 8], hi, lo);
        size_t base = (size_t)n * KP3 + k;
        Wt[base] = hi; Wt[base + 1024] = hi; Wt[base + 2048] = lo;
    }
}

// ------------------------- universal GEMM (K-chunk 64, 2-stage) -------------------------
// epi: 0 Qpack, 1 Kpack, 2 VTpack, 3 plain(+bias) -> outf
#define LDS2 72   // 144B stride: conflict-free ldmatrix

__global__ __launch_bounds__(256) void gemm_u(
    const bf16* __restrict__ Abase, const bf16* __restrict__ Wbase,
    float* __restrict__ outf, bf16* __restrict__ outq,
    bf16* __restrict__ outk, bf16* __restrict__ outvt,
    const float* __restrict__ b0, const float* __restrict__ b1,
    const float* __restrict__ b2, int fixedMode)
{
    extern __shared__ char smem[];
    const int tid = threadIdx.x, wid = tid >> 5, lane = tid & 31;
    const int m0 = blockIdx.y * 128, n0 = blockIdx.x * 128;
    const int z = blockIdx.z;
    const int epi = (fixedMode < 0) ? z : fixedMode;

    constexpr int BUF = 128 * LDS2 * 2;   // 18432
    const uint32_t sb = s2u(smem);
    const uint32_t uA[2] = { sb, sb + BUF };
    const uint32_t uB[2] = { sb + 2 * BUF, sb + 3 * BUF };

    const bf16* Ab = Abase + ((fixedMode < 0) ? (size_t)z * ASLAB : 0) + (size_t)m0 * KP3;
    const bf16* Bb = Wbase + ((fixedMode < 0) ? (size_t)z * WSLAB : 0) + (size_t)n0 * KP3;
    const float* bias = (epi == 0) ? b0 : (epi == 1) ? b1 : (epi == 2) ? b2 : b0;
    const float scale = (epi == 0) ? 0.125f : 1.0f;
    constexpr int nC = KP3 / 64;   // 48

    auto loadChunk = [&](int c, int buf) {
        const bf16* ap = Ab + c * 64;
        const bf16* bp = Bb + c * 64;
        #pragma unroll
        for (int p = 0; p < 4; p++) {
            int idx = tid + p * 256;
            int r = idx >> 3, sg = idx & 7;
            CP_ASYNC16(uA[buf] + r * (LDS2 * 2) + sg * 16,
                       (const char*)(ap + (size_t)r * KP3) + sg * 16);
        }
        #pragma unroll
        for (int p = 0; p < 4; p++) {
            int idx = tid + p * 256;
            int r = idx >> 3, sg = idx & 7;
            CP_ASYNC16(uB[buf] + r * (LDS2 * 2) + sg * 16,
                       (const char*)(bp + (size_t)r * KP3) + sg * 16);
        }
        CP_COMMIT();
    };

    float acc[2][8][4];
    #pragma unroll
    for (int i = 0; i < 2; i++)
        #pragma unroll
        for (int j = 0; j < 8; j++)
            #pragma unroll
            for (int q = 0; q < 4; q++) acc[i][j][q] = 0.f;

    const int wm = (wid & 3) * 32;
    const int wn = (wid >> 2) * 64;

    loadChunk(0, 0);
    for (int c = 0; c < nC; c++) {
        int buf = c & 1;
        if (c + 1 < nC) { loadChunk(c + 1, (c + 1) & 1); CP_WAIT(1); }
        else CP_WAIT(0);
        __syncthreads();
        #pragma unroll
        for (int ks = 0; ks < 4; ks++) {
            uint32_t a[2][4];
            #pragma unroll
            for (int im = 0; im < 2; im++) {
                uint32_t addr = uA[buf] +
                    ((wm + im * 16 + (lane & 15)) * LDS2 + ks * 16 + (lane >> 4) * 8) * 2;
                ldm_x4(a[im], addr);
            }
            uint32_t b[4][4];
            #pragma unroll
            for (int ig = 0; ig < 4; ig++) {
                uint32_t addr = uB[buf] +
                    ((wn + ig * 16 + (lane & 7) + ((lane >> 4) << 3)) * LDS2
                     + ks * 16 + (((lane >> 3) & 1) << 3)) * 2;
                ldm_x4(b[ig], addr);
            }
            #pragma unroll
            for (int im = 0; im < 2; im++)
                #pragma unroll
                for (int ig = 0; ig < 4; ig++) {
                    mma16816(acc[im][ig * 2],     a[im], &b[ig][0]);
                    mma16816(acc[im][ig * 2 + 1], a[im], &b[ig][2]);
                }
        }
        __syncthreads();
    }

    // ------------------- epilogues -------------------
    if (epi == 2) {
        float* stage = (float*)smem;
        #pragma unroll
        for (int im = 0; im < 2; im++)
            #pragma unroll
            for (int jn = 0; jn < 8; jn++)
                #pragma unroll
                for (int h2 = 0; h2 < 2; h2++)
                    #pragma unroll
                    for (int cc = 0; cc < 2; cc++) {
                        int ml = wm + im * 16 + (lane >> 2) + h2 * 8;
                        int nl = wn + jn * 8 + (lane & 3) * 2 + cc;
                        stage[ml * 130 + nl] = acc[im][jn][h2 * 2 + cc] + bias[n0 + nl];
                    }
        __syncthreads();
        {
            const int bI = m0 >> 11, sBase = m0 & (SS - 1);
            int gl = tid >> 1;
            int gn = n0 + gl;
            int h = gn >> 6, d = gn & 63;
            size_t base = ((size_t)((bI * NHD + h) * DH + d)) * KPV2;
            int s0 = (tid & 1) * 64;
            #pragma unroll 4
            for (int s = 0; s < 64; s++) {
                int sl = s0 + s;
                bf16 hi, lo; split3(stage[sl * 130 + gl], hi, lo);
                size_t sidx = base + sBase + sl;
                outvt[sidx] = hi; outvt[sidx + 2048] = lo;
            }
        }
    } else {
        #pragma unroll
        for (int im = 0; im < 2; im++)
            #pragma unroll
            for (int jn = 0; jn < 8; jn++)
                #pragma unroll
                for (int h2 = 0; h2 < 2; h2++)
                    #pragma unroll
                    for (int cc = 0; cc < 2; cc++) {
                        int m = m0 + wm + im * 16 + (lane >> 2) + h2 * 8;
                        int gn = n0 + wn + jn * 8 + (lane & 3) * 2 + cc;
                        float val = acc[im][jn][h2 * 2 + cc];
                        if (epi == 3) {
                            outf[(size_t)m * HH + gn] = val + bias[gn];
                        } else {
                            float v = (val + bias[gn]) * scale;
                            int h = gn >> 6, d = gn & 63;
                            int bI = m >> 11, sI = m & (SS - 1);
                            bf16 hi, lo; split3(v, hi, lo);
                            size_t base = ((size_t)(bI * NHD + h) * SS + sI) * KPS;
                            if (epi == 0) {  // Q: A-side [hi|lo|hi]
                                outq[base + d] = hi; outq[base + 64 + d] = lo; outq[base + 128 + d] = hi;
                            } else {         // K: B-side [hi|hi|lo]
                                outk[base + d] = hi; outk[base + 64 + d] = hi; outk[base + 128 + d] = lo;
                            }
                        }
                    }
    }
}

// ------------------------- fused flash attention (pipelined) -------------------------
#define KSTR 200
#define VSTR 136
#define KBUF (128*KSTR*2)         // 51200
#define VBUF (2*64*VSTR*2)        // 34816 (hi+lo)

__global__ __launch_bounds__(256, 1) void flash_k(
    const bf16* __restrict__ Qp, const bf16* __restrict__ Kp,
    const bf16* __restrict__ Vt, bf16* __restrict__ Ctx)
{
    extern __shared__ char smem[];
    const int tid = threadIdx.x, wid = tid >> 5, lane = tid & 31;
    const int qt = blockIdx.x, bh = blockIdx.y;
    const int b_ = bh >> 4, h_ = bh & 15;
    const uint32_t sb = s2u(smem);
    const uint32_t uK = sb;
    const uint32_t uV0 = sb + KBUF;

    const bf16* Qb = Qp + ((size_t)bh * SS + qt * 128) * KPS;
    const bf16* Kb = Kp + (size_t)bh * SS * KPS;
    const bf16* Vb = Vt + (size_t)bh * DH * KPV2;

    // G0: Q staged into V region; G1: K0 into uK (concurrent)
    #pragma unroll
    for (int p = 0; p < 12; p++) {
        int idx = tid + p * 256;
        int r = idx / 24, sg = idx % 24;
        CP_ASYNC16(uV0 + r * (KSTR * 2) + sg * 16,
                   (const char*)(Qb + (size_t)r * KPS) + sg * 16);
    }
    CP_COMMIT();
    #pragma unroll
    for (int p = 0; p < 12; p++) {
        int idx = tid + p * 256;
        int r = idx / 24, sg = idx % 24;
        CP_ASYNC16(uK + r * (KSTR * 2) + sg * 16,
                   (const char*)(Kb + (size_t)r * KPS) + sg * 16);
    }
    CP_COMMIT();
    CP_WAIT(1); __syncthreads();            // Q ready (K0 in flight)

    uint32_t qf[12][4];
    {
        int rbase = wid * 16 + (lane & 15);
        #pragma unroll
        for (int kc = 0; kc < 12; kc++)
            ldm_x4(qf[kc], uV0 + (rbase * KSTR + kc * 16 + (lane >> 4) * 8) * 2);
    }
    __syncthreads();                         // done reading Q stage

    // G2: V0 into buffer 0
    #pragma unroll
    for (int p = 0; p < 4; p++) {
        int idx = tid + p * 256;
        int r = idx >> 4, sg = idx & 15;
        const char* s = (const char*)(Vb + (size_t)r * KPV2) + sg * 16;
        CP_ASYNC16(uV0 + r * (VSTR * 2) + sg * 16, s);
        CP_ASYNC16(uV0 + 17408 + r * (VSTR * 2) + sg * 16, s + 4096);
    }
    CP_COMMIT();

    float oacc[8][4];
    #pragma unroll
    for (int j = 0; j < 8; j++)
        #pragma unroll
        for (int q = 0; q < 4; q++) oacc[j][q] = 0.f;
    float M0 = -1e30f, M1 = -1e30f, L0 = 0.f, L1 = 0.f;

    for (int i = 0; i < 16; i++) {
        const int kt = i * 128, vb = i & 1;
        const uint32_t uVh = uV0 + vb * VBUF;
        const uint32_t uVl = uVh + 17408;
        const bool hasNext = (i < 15);

        CP_WAIT(1); __syncthreads();         // K_i ready

        // S = Q K^T
        float sc[16][4];
        #pragma unroll
        for (int t = 0; t < 16; t++)
            #pragma unroll
            for (int q = 0; q < 4; q++) sc[t][q] = 0.f;
        #pragma unroll
        for (int kc = 0; kc < 12; kc++) {
            #pragma unroll
            for (int kg = 0; kg < 8; kg++) {
                uint32_t b[4];
                uint32_t addr = uK + ((kg * 16 + (lane & 7) + ((lane >> 4) << 3)) * KSTR
                                      + kc * 16 + (((lane >> 3) & 1) << 3)) * 2;
                ldm_x4(b, addr);
                mma16816(sc[kg * 2],     qf[kc], b);
                mma16816(sc[kg * 2 + 1], qf[kc], b + 2);
            }
        }
        __syncthreads();                     // uK free

        if (hasNext) {                       // issue K_{i+1} (overlaps softmax+PV)
            const bf16* kp2 = Kb + (size_t)(kt + 128) * KPS;
            #pragma unroll
            for (int p = 0; p < 12; p++) {
                int idx = tid + p * 256;
                int r = idx / 24, sg = idx % 24;
                CP_ASYNC16(uK + r * (KSTR * 2) + sg * 16,
                           (const char*)(kp2 + (size_t)r * KPS) + sg * 16);
            }
            CP_COMMIT();
        }

        // online softmax
        float m0 = -1e30f, m1 = -1e30f;
        #pragma unroll
        for (int t = 0; t < 16; t++) {
            m0 = fmaxf(m0, fmaxf(sc[t][0], sc[t][1]));
            m1 = fmaxf(m1, fmaxf(sc[t][2], sc[t][3]));
        }
        #pragma unroll
        for (int off = 1; off <= 2; off <<= 1) {
            m0 = fmaxf(m0, __shfl_xor_sync(0xffffffffu, m0, off));
            m1 = fmaxf(m1, __shfl_xor_sync(0xffffffffu, m1, off));
        }
        float nM0 = fmaxf(M0, m0), nM1 = fmaxf(M1, m1);
        float a0 = __expf(M0 - nM0), a1 = __expf(M1 - nM1);
        M0 = nM0; M1 = nM1;
        float s0 = 0.f, s1 = 0.f;
        #pragma unroll
        for (int t = 0; t < 16; t++) {
            sc[t][0] = __expf(sc[t][0] - M0); s0 += sc[t][0];
            sc[t][1] = __expf(sc[t][1] - M0); s0 += sc[t][1];
            sc[t][2] = __expf(sc[t][2] - M1); s1 += sc[t][2];
            sc[t][3] = __expf(sc[t][3] - M1); s1 += sc[t][3];
        }
        #pragma unroll
        for (int off = 1; off <= 2; off <<= 1) {
            s0 += __shfl_xor_sync(0xffffffffu, s0, off);
            s1 += __shfl_xor_sync(0xffffffffu, s1, off);
        }
        L0 = L0 * a0 + s0; L1 = L1 * a1 + s1;
        #pragma unroll
        for (int j = 0; j < 8; j++) {
            oacc[j][0] *= a0; oacc[j][1] *= a0;
            oacc[j][2] *= a1; oacc[j][3] *= a1;
        }

        if (hasNext) CP_WAIT(1); else CP_WAIT(0);   // V_i ready
        __syncthreads();

        if (hasNext) {                       // issue V_{i+1} into other buffer
            const uint32_t dVh = uV0 + (vb ^ 1) * VBUF;
            #pragma unroll
            for (int p = 0; p < 4; p++) {
                int idx = tid + p * 256;
                int r = idx >> 4, sg = idx & 15;
                const char* s = (const char*)(Vb + (size_t)r * KPV2 + kt + 128) + sg * 16;
                CP_ASYNC16(dVh + r * (VSTR * 2) + sg * 16, s);
                CP_ASYNC16(dVh + 17408 + r * (VSTR * 2) + sg * 16, s + 4096);
            }
            CP_COMMIT();
        }

        // PV: 3 chains
        #pragma unroll
        for (int j = 0; j < 8; j++) {
            uint32_t ph[4], pl[4];
            float c00 = sc[2*j][0],   c01 = sc[2*j][1];
            float c02 = sc[2*j][2],   c03 = sc[2*j][3];
            float c10 = sc[2*j+1][0], c11 = sc[2*j+1][1];
            float c12 = sc[2*j+1][2], c13 = sc[2*j+1][3];
            float h00 = __bfloat162float(__float2bfloat16(c00));
            float h01 = __bfloat162float(__float2bfloat16(c01));
            float h02 = __bfloat162float(__float2bfloat16(c02));
            float h03 = __bfloat162float(__float2bfloat16(c03));
            float h10 = __bfloat162float(__float2bfloat16(c10));
            float h11 = __bfloat162float(__float2bfloat16(c11));
            float h12 = __bfloat162float(__float2bfloat16(c12));
            float h13 = __bfloat162float(__float2bfloat16(c13));
            ph[0] = pk2(h00, h01); ph[1] = pk2(h02, h03);
            ph[2] = pk2(h10, h11); ph[3] = pk2(h12, h13);
            pl[0] = pk2(c00 - h00, c01 - h01); pl[1] = pk2(c02 - h02, c03 - h03);
            pl[2] = pk2(c10 - h10, c11 - h11); pl[3] = pk2(c12 - h12, c13 - h13);

            uint32_t koff = (j * 16 + (((lane >> 3) & 1) << 3)) * 2;
            uint32_t rsel = (lane & 7) + ((lane >> 4) << 3);
            #pragma unroll
            for (int dg = 0; dg < 4; dg++) {
                uint32_t row = dg * 16 + rsel;
                uint32_t bh4[4], bl4[4];
                ldm_x4(bh4, uVh + row * (VSTR * 2) + koff);
                ldm_x4(bl4, uVl + row * (VSTR * 2) + koff);
                mma16816(oacc[dg * 2],     ph, bh4);
                mma16816(oacc[dg * 2 + 1], ph, bh4 + 2);
                mma16816(oacc[dg * 2],     pl, bh4);
                mma16816(oacc[dg * 2 + 1], pl, bh4 + 2);
                mma16816(oacc[dg * 2],     ph, bl4);
                mma16816(oacc[dg * 2 + 1], ph, bl4 + 2);
            }
        }
    }

    // epilogue: normalize + packed ctx write [hi|lo|hi]
    float i0 = 1.f / L0, i1 = 1.f / L1;
    int r = lane >> 2;
    int q0 = qt * 128 + wid * 16;
    size_t row0 = ((size_t)(b_ * SS + q0 + r)) * KP3;
    size_t row1 = ((size_t)(b_ * SS + q0 + r + 8)) * KP3;
    int cbase = h_ * DH + (lane & 3) * 2;
    #pragma unroll
    for (int t = 0; t < 8; t++) {
        int col = cbase + t * 8;
        float v0 = oacc[t][0] * i0, v1 = oacc[t][1] * i0;
        float w0 = oacc[t][2] * i1, w1 = oacc[t][3] * i1;
        float vh0 = __bfloat162float(__float2bfloat16(v0));
        float vh1 = __bfloat162float(__float2bfloat16(v1));
        float wh0 = __bfloat162float(__float2bfloat16(w0));
        float wh1 = __bfloat162float(__float2bfloat16(w1));
        *(uint32_t*)&Ctx[row0 + col]        = pk2(vh0, vh1);
        *(uint32_t*)&Ctx[row0 + 1024 + col] = pk2(v0 - vh0, v1 - vh1);
        *(uint32_t*)&Ctx[row0 + 2048 + col] = pk2(vh0, vh1);
        *(uint32_t*)&Ctx[row1 + col]        = pk2(wh0, wh1);
        *(uint32_t*)&Ctx[row1 + 1024 + col] = pk2(w0 - wh0, w1 - wh1);
        *(uint32_t*)&Ctx[row1 + 2048 + col] = pk2(wh0, wh1);
    }
}

// ------------------------- launch -------------------------
extern "C" void kernel_launch(void* const* d_in, const int* in_sizes, int n_in,
                              void* d_out, int out_size)
{
    const float* key   = (const float*)d_in[0];
    const float* value = (const float*)d_in[1];
    const float* query = (const float*)d_in[2];
    const float* wq = (const float*)d_in[3];
    const float* bq = (const float*)d_in[4];
    const float* wk = (const float*)d_in[5];
    const float* bk = (const float*)d_in[6];
    const float* wv = (const float*)d_in[7];
    const float* bv = (const float*)d_in[8];
    const float* wo = (const float*)d_in[9];
    const float* bo = (const float*)d_in[10];
    float* out = (float*)d_out;

    bf16 *xp, *wt, *qp, *kp, *vt;
    cudaGetSymbolAddress((void**)&xp, g_Xp);
    cudaGetSymbolAddress((void**)&wt, g_Wt);
    cudaGetSymbolAddress((void**)&qp, g_Qp);
    cudaGetSymbolAddress((void**)&kp, g_Kp);
    cudaGetSymbolAddress((void**)&vt, g_Vt);

    constexpr int SMG  = 4 * 18432;                 // 73728
    constexpr int SMFL = KBUF + 2 * VBUF;           // 120832
    cudaFuncSetAttribute(gemm_u,  cudaFuncAttributeMaxDynamicSharedMemorySize, SMG);
    cudaFuncSetAttribute(flash_k, cudaFuncAttributeMaxDynamicSharedMemorySize, SMFL);

    // pack all weights (z=0..3) and all activations (z=0..2)
    pack_wt_k<<<dim3(32, 32, 4), 256>>>(wq, wk, wv, wo, wt);
    pack_a_k<<<dim3(MTOT * HH / 1024, 3), 256>>>(query, key, value, xp);

    // merged QKV projections (z: 0=Q,1=K,2=Vt)
    gemm_u<<<dim3(8, 64, 3), 256, SMG>>>(xp, wt, nullptr, qp, kp, vt,
                                         bq, bk, bv, -1);

    // fused attention -> packed ctx in Xp slab 0
    flash_k<<<dim3(16, 64), 256, SMFL>>>(qp, kp, vt, xp);

    // output projection
    gemm_u<<<dim3(8, 64, 1), 256, SMG>>>(xp, wt + 3 * WSLAB, out,
                                         nullptr, nullptr, nullptr,
                                         bo, bo, bo, 3);
}

// round 7
// speedup vs baseline: 2.7316x; 1.1312x over previous
#include <cuda_runtime.h>
#include <cuda_bf16.h>
#include <cstdint>

typedef __nv_bfloat16 bf16;

#define BB 4
#define SS 2048
#define NHD 16
#define DH 64
#define HH 1024
#define MTOT (BB*SS)     // 8192
#define KP3 3072         // 3*1024 packed K (projections)
#define KPS 192          // 3*64   packed K (QK)
#define KPV2 4096        // 2*2048 packed V (hi | lo)

#define ASLAB ((size_t)MTOT*KP3)
#define WSLAB ((size_t)HH*KP3)
#define LOG2E 1.4426950408889634f

// ------------------------- scratch (device globals) -------------------------
__device__ bf16  g_Xp[3*ASLAB];                 // packed acts (q,k,v) / ctx in slab0
__device__ bf16  g_Wt[4*WSLAB];                 // packed weights^T
__device__ bf16  g_Qp[(size_t)BB*NHD*SS*KPS];
__device__ bf16  g_Kp[(size_t)BB*NHD*SS*KPS];
__device__ bf16  g_Vt[(size_t)BB*NHD*DH*KPV2];

// ------------------------- helpers -------------------------
__device__ __forceinline__ uint32_t s2u(const void* p) {
    uint32_t a;
    asm("{ .reg .u64 t; cvta.to.shared.u64 t, %1; cvt.u32.u64 %0, t; }" : "=r"(a) : "l"(p));
    return a;
}
#define CP_ASYNC16(dst, src) \
    asm volatile("cp.async.cg.shared.global [%0], [%1], 16;" :: "r"(dst), "l"(src))
#define CP_COMMIT() asm volatile("cp.async.commit_group;" ::: "memory")
#define CP_WAIT(n)  asm volatile("cp.async.wait_group %0;" :: "n"(n) : "memory")

__device__ __forceinline__ void ldm_x4(uint32_t* r, uint32_t addr) {
    asm volatile("ldmatrix.sync.aligned.m8n8.x4.shared.b16 {%0,%1,%2,%3}, [%4];"
        : "=r"(r[0]), "=r"(r[1]), "=r"(r[2]), "=r"(r[3]) : "r"(addr));
}
__device__ __forceinline__ void mma16816(float* d, const uint32_t* a, const uint32_t* b) {
    asm volatile("mma.sync.aligned.m16n8k16.row.col.f32.bf16.bf16.f32 "
        "{%0,%1,%2,%3}, {%4,%5,%6,%7}, {%8,%9}, {%0,%1,%2,%3};"
        : "+f"(d[0]), "+f"(d[1]), "+f"(d[2]), "+f"(d[3])
        : "r"(a[0]), "r"(a[1]), "r"(a[2]), "r"(a[3]), "r"(b[0]), "r"(b[1]));
}
__device__ __forceinline__ void split3(float f, bf16& hi, bf16& lo) {
    hi = __float2bfloat16(f);
    lo = __float2bfloat16(f - __bfloat162float(hi));
}
__device__ __forceinline__ uint32_t pk2(float lo, float hi) {
    uint32_t r;
    asm("cvt.rn.bf16x2.f32 %0, %1, %2;" : "=r"(r) : "f"(hi), "f"(lo));
    return r;
}
__device__ __forceinline__ float ex2f(float x) {
    float r;
    asm("ex2.approx.ftz.f32 %0, %1;" : "=f"(r) : "f"(x));
    return r;
}

// ------------------------- pack kernels -------------------------
__global__ __launch_bounds__(256) void pack_a_k(
    const float* __restrict__ q, const float* __restrict__ k,
    const float* __restrict__ v, bf16* __restrict__ xpBase)
{
    int z = blockIdx.y;
    const float* x = (z == 0) ? q : (z == 1) ? k : v;
    bf16* xp = xpBase + (size_t)z * ASLAB;
    int i = blockIdx.x * 256 + threadIdx.x;
    int row = i >> 8;
    int k4 = (i & 255) << 2;
    float4 f = *(const float4*)&x[((size_t)row << 10) + k4];
    float fv[4] = {f.x, f.y, f.z, f.w};
    bf16 h[4], l[4];
    #pragma unroll
    for (int qq = 0; qq < 4; qq++) split3(fv[qq], h[qq], l[qq]);
    size_t base = (size_t)row * KP3 + k4;
    *(__nv_bfloat162*)&xp[base]        = __nv_bfloat162(h[0], h[1]);
    *(__nv_bfloat162*)&xp[base + 2]    = __nv_bfloat162(h[2], h[3]);
    *(__nv_bfloat162*)&xp[base + 1024] = __nv_bfloat162(l[0], l[1]);
    *(__nv_bfloat162*)&xp[base + 1026] = __nv_bfloat162(l[2], l[3]);
    *(__nv_bfloat162*)&xp[base + 2048] = __nv_bfloat162(h[0], h[1]);
    *(__nv_bfloat162*)&xp[base + 2050] = __nv_bfloat162(h[2], h[3]);
}

__global__ __launch_bounds__(256) void pack_wt_k(
    const float* __restrict__ wq, const float* __restrict__ wk,
    const float* __restrict__ wv, const float* __restrict__ wo,
    bf16* __restrict__ wtBase)
{
    __shared__ float t[32][33];
    int z = blockIdx.z;
    const float* W = (z == 0) ? wq : (z == 1) ? wk : (z == 2) ? wv : wo;
    bf16* Wt = wtBase + (size_t)z * WSLAB;
    int tx = threadIdx.x & 31, ty = threadIdx.x >> 5;
    int n0 = blockIdx.x * 32, k0 = blockIdx.y * 32;
    #pragma unroll
    for (int r = 0; r < 4; r++) {
        int k = k0 + ty + r * 8;
        t[ty + r * 8][tx] = W[(size_t)k * HH + n0 + tx];
    }
    __syncthreads();
    #pragma unroll
    for (int r = 0; r < 4; r++) {
        int n = n0 + ty + r * 8;
        int k = k0 + tx;
        bf16 hi, lo; split3(t[tx][ty + r * 8], hi, lo);
        size_t base = (size_t)n * KP3 + k;
        Wt[base] = hi; Wt[base + 1024] = hi; Wt[base + 2048] = lo;
    }
}

// ------------------------- universal GEMM: CTA 128x256, warp 64x64 -------------------------
// epi: 0 Qpack, 1 Kpack, 2 VTpack, 3 plain(+bias)
#define LDS2 72
#define BUFA (128*LDS2*2)   // 18432
#define BUFB (256*LDS2*2)   // 36864
#define STG_STR 258

__global__ __launch_bounds__(256) void gemm_u(
    const bf16* __restrict__ Abase, const bf16* __restrict__ Wbase,
    float* __restrict__ outf, bf16* __restrict__ outq,
    bf16* __restrict__ outk, bf16* __restrict__ outvt,
    const float* __restrict__ b0, const float* __restrict__ b1,
    const float* __restrict__ b2, int fixedMode)
{
    extern __shared__ char smem[];
    const int tid = threadIdx.x, wid = tid >> 5, lane = tid & 31;
    const int m0 = blockIdx.y * 128, n0 = blockIdx.x * 256;
    const int z = blockIdx.z;
    const int epi = (fixedMode < 0) ? z : fixedMode;

    const uint32_t sb = s2u(smem);
    const uint32_t uA[2] = { sb, sb + BUFA };
    const uint32_t uB[2] = { sb + 2 * BUFA, sb + 2 * BUFA + BUFB };

    const bf16* Ab = Abase + ((fixedMode < 0) ? (size_t)z * ASLAB : 0) + (size_t)m0 * KP3;
    const bf16* Bb = Wbase + ((fixedMode < 0) ? (size_t)z * WSLAB : 0) + (size_t)n0 * KP3;
    const float* bias = (epi == 0) ? b0 : (epi == 1) ? b1 : (epi == 2) ? b2 : b0;
    // Q pack folds 1/sqrt(DH) * log2(e) so softmax can use raw ex2
    const float scale = (epi == 0) ? (0.125f * LOG2E) : 1.0f;
    constexpr int nC = KP3 / 64;   // 48

    auto loadChunk = [&](int c, int buf) {
        const bf16* ap = Ab + c * 64;
        const bf16* bp = Bb + c * 64;
        #pragma unroll
        for (int p = 0; p < 4; p++) {
            int idx = tid + p * 256;
            int r = idx >> 3, sg = idx & 7;
            CP_ASYNC16(uA[buf] + r * (LDS2 * 2) + sg * 16,
                       (const char*)(ap + (size_t)r * KP3) + sg * 16);
        }
        #pragma unroll
        for (int p = 0; p < 8; p++) {
            int idx = tid + p * 256;
            int r = idx >> 3, sg = idx & 7;
            CP_ASYNC16(uB[buf] + r * (LDS2 * 2) + sg * 16,
                       (const char*)(bp + (size_t)r * KP3) + sg * 16);
        }
        CP_COMMIT();
    };

    float acc[4][8][4];
    #pragma unroll
    for (int i = 0; i < 4; i++)
        #pragma unroll
        for (int j = 0; j < 8; j++)
            #pragma unroll
            for (int q = 0; q < 4; q++) acc[i][j][q] = 0.f;

    const int wm = (wid & 1) * 64;       // 2 warps in M
    const int wn = (wid >> 1) * 64;      // 4 warps in N

    loadChunk(0, 0);
    for (int c = 0; c < nC; c++) {
        int buf = c & 1;
        if (c + 1 < nC) { loadChunk(c + 1, (c + 1) & 1); CP_WAIT(1); }
        else CP_WAIT(0);
        __syncthreads();
        #pragma unroll
        for (int ks = 0; ks < 4; ks++) {
            uint32_t a[4][4];
            #pragma unroll
            for (int im = 0; im < 4; im++) {
                uint32_t addr = uA[buf] +
                    ((wm + im * 16 + (lane & 15)) * LDS2 + ks * 16 + (lane >> 4) * 8) * 2;
                ldm_x4(a[im], addr);
            }
            uint32_t b[4][4];
            #pragma unroll
            for (int ig = 0; ig < 4; ig++) {
                uint32_t addr = uB[buf] +
                    ((wn + ig * 16 + (lane & 7) + ((lane >> 4) << 3)) * LDS2
                     + ks * 16 + (((lane >> 3) & 1) << 3)) * 2;
                ldm_x4(b[ig], addr);
            }
            #pragma unroll
            for (int im = 0; im < 4; im++)
                #pragma unroll
                for (int ig = 0; ig < 4; ig++) {
                    mma16816(acc[im][ig * 2],     a[im], &b[ig][0]);
                    mma16816(acc[im][ig * 2 + 1], a[im], &b[ig][2]);
                }
        }
        __syncthreads();
    }

    // ------------------- epilogues -------------------
    if (epi == 2) {
        float* stage = (float*)smem;
        #pragma unroll
        for (int im = 0; im < 4; im++)
            #pragma unroll
            for (int jn = 0; jn < 8; jn++)
                #pragma unroll
                for (int h2 = 0; h2 < 2; h2++)
                    #pragma unroll
                    for (int cc = 0; cc < 2; cc++) {
                        int ml = wm + im * 16 + (lane >> 2) + h2 * 8;
                        int nl = wn + jn * 8 + (lane & 3) * 2 + cc;
                        stage[ml * STG_STR + nl] = acc[im][jn][h2 * 2 + cc] + bias[n0 + nl];
                    }
        __syncthreads();
        {
            const int bI = m0 >> 11, sBase = m0 & (SS - 1);
            int gl = tid;                    // one n per thread (256 n)
            int gn = n0 + gl;
            int h = gn >> 6, d = gn & 63;
            size_t base = ((size_t)((bI * NHD + h) * DH + d)) * KPV2;
            #pragma unroll 4
            for (int sl = 0; sl < 128; sl++) {
                bf16 hi, lo; split3(stage[sl * STG_STR + gl], hi, lo);
                size_t sidx = base + sBase + sl;
                outvt[sidx] = hi; outvt[sidx + 2048] = lo;
            }
        }
    } else if (epi == 3) {
        #pragma unroll
        for (int im = 0; im < 4; im++)
            #pragma unroll
            for (int jn = 0; jn < 8; jn++)
                #pragma unroll
                for (int h2 = 0; h2 < 2; h2++) {
                    int m = m0 + wm + im * 16 + (lane >> 2) + h2 * 8;
                    int gn = n0 + wn + jn * 8 + (lane & 3) * 2;
                    float2 r2;
                    r2.x = acc[im][jn][h2 * 2]     + bias[gn];
                    r2.y = acc[im][jn][h2 * 2 + 1] + bias[gn + 1];
                    *(float2*)&outf[(size_t)m * HH + gn] = r2;
                }
    } else {
        #pragma unroll
        for (int im = 0; im < 4; im++)
            #pragma unroll
            for (int jn = 0; jn < 8; jn++)
                #pragma unroll
                for (int h2 = 0; h2 < 2; h2++) {
                    int m = m0 + wm + im * 16 + (lane >> 2) + h2 * 8;
                    int gn = n0 + wn + jn * 8 + (lane & 3) * 2;
                    float v0 = (acc[im][jn][h2 * 2]     + bias[gn])     * scale;
                    float v1 = (acc[im][jn][h2 * 2 + 1] + bias[gn + 1]) * scale;
                    int h = gn >> 6, d = gn & 63;
                    int bI = m >> 11, sI = m & (SS - 1);
                    bf16 h0, l0, h1, l1;
                    split3(v0, h0, l0); split3(v1, h1, l1);
                    float fh0 = __bfloat162float(h0), fh1 = __bfloat162float(h1);
                    float fl0 = __bfloat162float(l0), fl1 = __bfloat162float(l1);
                    size_t base = ((size_t)(bI * NHD + h) * SS + sI) * KPS;
                    if (epi == 0) {  // Q: A-side [hi|lo|hi]
                        *(uint32_t*)&outq[base + d]       = pk2(fh0, fh1);
                        *(uint32_t*)&outq[base + 64 + d]  = pk2(fl0, fl1);
                        *(uint32_t*)&outq[base + 128 + d] = pk2(fh0, fh1);
                    } else {         // K: B-side [hi|hi|lo]
                        *(uint32_t*)&outk[base + d]       = pk2(fh0, fh1);
                        *(uint32_t*)&outk[base + 64 + d]  = pk2(fh0, fh1);
                        *(uint32_t*)&outk[base + 128 + d] = pk2(fl0, fl1);
                    }
                }
    }
}

// ------------------------- fused flash attention (pipelined) -------------------------
#define KSTR 200
#define VSTR 136
#define KBUF (128*KSTR*2)         // 51200
#define VBUF (2*64*VSTR*2)        // 34816

__global__ __launch_bounds__(256, 1) void flash_k(
    const bf16* __restrict__ Qp, const bf16* __restrict__ Kp,
    const bf16* __restrict__ Vt, bf16* __restrict__ Ctx)
{
    extern __shared__ char smem[];
    const int tid = threadIdx.x, wid = tid >> 5, lane = tid & 31;
    const int qt = blockIdx.x, bh = blockIdx.y;
    const int b_ = bh >> 4, h_ = bh & 15;
    const uint32_t sb = s2u(smem);
    const uint32_t uK = sb;
    const uint32_t uV0 = sb + KBUF;

    const bf16* Qb = Qp + ((size_t)bh * SS + qt * 128) * KPS;
    const bf16* Kb = Kp + (size_t)bh * SS * KPS;
    const bf16* Vb = Vt + (size_t)bh * DH * KPV2;

    #pragma unroll
    for (int p = 0; p < 12; p++) {
        int idx = tid + p * 256;
        int r = idx / 24, sg = idx % 24;
        CP_ASYNC16(uV0 + r * (KSTR * 2) + sg * 16,
                   (const char*)(Qb + (size_t)r * KPS) + sg * 16);
    }
    CP_COMMIT();
    #pragma unroll
    for (int p = 0; p < 12; p++) {
        int idx = tid + p * 256;
        int r = idx / 24, sg = idx % 24;
        CP_ASYNC16(uK + r * (KSTR * 2) + sg * 16,
                   (const char*)(Kb + (size_t)r * KPS) + sg * 16);
    }
    CP_COMMIT();
    CP_WAIT(1); __syncthreads();

    uint32_t qf[12][4];
    {
        int rbase = wid * 16 + (lane & 15);
        #pragma unroll
        for (int kc = 0; kc < 12; kc++)
            ldm_x4(qf[kc], uV0 + (rbase * KSTR + kc * 16 + (lane >> 4) * 8) * 2);
    }
    __syncthreads();

    #pragma unroll
    for (int p = 0; p < 4; p++) {
        int idx = tid + p * 256;
        int r = idx >> 4, sg = idx & 15;
        const char* s = (const char*)(Vb + (size_t)r * KPV2) + sg * 16;
        CP_ASYNC16(uV0 + r * (VSTR * 2) + sg * 16, s);
        CP_ASYNC16(uV0 + 17408 + r * (VSTR * 2) + sg * 16, s + 4096);
    }
    CP_COMMIT();

    float oacc[8][4];
    #pragma unroll
    for (int j = 0; j < 8; j++)
        #pragma unroll
        for (int q = 0; q < 4; q++) oacc[j][q] = 0.f;
    float M0 = -1e30f, M1 = -1e30f, L0 = 0.f, L1 = 0.f;

    for (int i = 0; i < 16; i++) {
        const int kt = i * 128, vb = i & 1;
        const uint32_t uVh = uV0 + vb * VBUF;
        const uint32_t uVl = uVh + 17408;
        const bool hasNext = (i < 15);

        CP_WAIT(1); __syncthreads();

        float sc[16][4];
        #pragma unroll
        for (int t = 0; t < 16; t++)
            #pragma unroll
            for (int q = 0; q < 4; q++) sc[t][q] = 0.f;
        #pragma unroll
        for (int kc = 0; kc < 12; kc++) {
            #pragma unroll
            for (int kg = 0; kg < 8; kg++) {
                uint32_t b[4];
                uint32_t addr = uK + ((kg * 16 + (lane & 7) + ((lane >> 4) << 3)) * KSTR
                                      + kc * 16 + (((lane >> 3) & 1) << 3)) * 2;
                ldm_x4(b, addr);
                mma16816(sc[kg * 2],     qf[kc], b);
                mma16816(sc[kg * 2 + 1], qf[kc], b + 2);
            }
        }
        __syncthreads();

        if (hasNext) {
            const bf16* kp2 = Kb + (size_t)(kt + 128) * KPS;
            #pragma unroll
            for (int p = 0; p < 12; p++) {
                int idx = tid + p * 256;
                int r = idx / 24, sg = idx % 24;
                CP_ASYNC16(uK + r * (KSTR * 2) + sg * 16,
                           (const char*)(kp2 + (size_t)r * KPS) + sg * 16);
            }
            CP_COMMIT();
        }

        // online softmax in log2 domain (Q pre-scaled by log2e/8)
        float m0 = -1e30f, m1 = -1e30f;
        #pragma unroll
        for (int t = 0; t < 16; t++) {
            m0 = fmaxf(m0, fmaxf(sc[t][0], sc[t][1]));
            m1 = fmaxf(m1, fmaxf(sc[t][2], sc[t][3]));
        }
        #pragma unroll
        for (int off = 1; off <= 2; off <<= 1) {
            m0 = fmaxf(m0, __shfl_xor_sync(0xffffffffu, m0, off));
            m1 = fmaxf(m1, __shfl_xor_sync(0xffffffffu, m1, off));
        }
        float nM0 = fmaxf(M0, m0), nM1 = fmaxf(M1, m1);
        float a0 = ex2f(M0 - nM0), a1 = ex2f(M1 - nM1);
        M0 = nM0; M1 = nM1;
        float s0 = 0.f, s1 = 0.f;
        #pragma unroll
        for (int t = 0; t < 16; t++) {
            sc[t][0] = ex2f(sc[t][0] - M0); s0 += sc[t][0];
            sc[t][1] = ex2f(sc[t][1] - M0); s0 += sc[t][1];
            sc[t][2] = ex2f(sc[t][2] - M1); s1 += sc[t][2];
            sc[t][3] = ex2f(sc[t][3] - M1); s1 += sc[t][3];
        }
        #pragma unroll
        for (int off = 1; off <= 2; off <<= 1) {
            s0 += __shfl_xor_sync(0xffffffffu, s0, off);
            s1 += __shfl_xor_sync(0xffffffffu, s1, off);
        }
        L0 = L0 * a0 + s0; L1 = L1 * a1 + s1;
        #pragma unroll
        for (int j = 0; j < 8; j++) {
            oacc[j][0] *= a0; oacc[j][1] *= a0;
            oacc[j][2] *= a1; oacc[j][3] *= a1;
        }

        if (hasNext) CP_WAIT(1); else CP_WAIT(0);
        __syncthreads();

        if (hasNext) {
            const uint32_t dVh = uV0 + (vb ^ 1) * VBUF;
            #pragma unroll
            for (int p = 0; p < 4; p++) {
                int idx = tid + p * 256;
                int r = idx >> 4, sg = idx & 15;
                const char* s = (const char*)(Vb + (size_t)r * KPV2 + kt + 128) + sg * 16;
                CP_ASYNC16(dVh + r * (VSTR * 2) + sg * 16, s);
                CP_ASYNC16(dVh + 17408 + r * (VSTR * 2) + sg * 16, s + 4096);
            }
            CP_COMMIT();
        }

        #pragma unroll
        for (int j = 0; j < 8; j++) {
            uint32_t ph[4], pl[4];
            float c00 = sc[2*j][0],   c01 = sc[2*j][1];
            float c02 = sc[2*j][2],   c03 = sc[2*j][3];
            float c10 = sc[2*j+1][0], c11 = sc[2*j+1][1];
            float c12 = sc[2*j+1][2], c13 = sc[2*j+1][3];
            float h00 = __bfloat162float(__float2bfloat16(c00));
            float h01 = __bfloat162float(__float2bfloat16(c01));
            float h02 = __bfloat162float(__float2bfloat16(c02));
            float h03 = __bfloat162float(__float2bfloat16(c03));
            float h10 = __bfloat162float(__float2bfloat16(c10));
            float h11 = __bfloat162float(__float2bfloat16(c11));
            float h12 = __bfloat162float(__float2bfloat16(c12));
            float h13 = __bfloat162float(__float2bfloat16(c13));
            ph[0] = pk2(h00, h01); ph[1] = pk2(h02, h03);
            ph[2] = pk2(h10, h11); ph[3] = pk2(h12, h13);
            pl[0] = pk2(c00 - h00, c01 - h01); pl[1] = pk2(c02 - h02, c03 - h03);
            pl[2] = pk2(c10 - h10, c11 - h11); pl[3] = pk2(c12 - h12, c13 - h13);

            uint32_t koff = (j * 16 + (((lane >> 3) & 1) << 3)) * 2;
            uint32_t rsel = (lane & 7) + ((lane >> 4) << 3);
            #pragma unroll
            for (int dg = 0; dg < 4; dg++) {
                uint32_t row = dg * 16 + rsel;
                uint32_t bh4[4], bl4[4];
                ldm_x4(bh4, uVh + row * (VSTR * 2) + koff);
                ldm_x4(bl4, uVl + row * (VSTR * 2) + koff);
                mma16816(oacc[dg * 2],     ph, bh4);
                mma16816(oacc[dg * 2 + 1], ph, bh4 + 2);
                mma16816(oacc[dg * 2],     pl, bh4);
                mma16816(oacc[dg * 2 + 1], pl, bh4 + 2);
                mma16816(oacc[dg * 2],     ph, bl4);
                mma16816(oacc[dg * 2 + 1], ph, bl4 + 2);
            }
        }
    }

    float i0 = 1.f / L0, i1 = 1.f / L1;
    int r = lane >> 2;
    int q0 = qt * 128 + wid * 16;
    size_t row0 = ((size_t)(b_ * SS + q0 + r)) * KP3;
    size_t row1 = ((size_t)(b_ * SS + q0 + r + 8)) * KP3;
    int cbase = h_ * DH + (lane & 3) * 2;
    #pragma unroll
    for (int t = 0; t < 8; t++) {
        int col = cbase + t * 8;
        float v0 = oacc[t][0] * i0, v1 = oacc[t][1] * i0;
        float w0 = oacc[t][2] * i1, w1 = oacc[t][3] * i1;
        float vh0 = __bfloat162float(__float2bfloat16(v0));
        float vh1 = __bfloat162float(__float2bfloat16(v1));
        float wh0 = __bfloat162float(__float2bfloat16(w0));
        float wh1 = __bfloat162float(__float2bfloat16(w1));
        *(uint32_t*)&Ctx[row0 + col]        = pk2(vh0, vh1);
        *(uint32_t*)&Ctx[row0 + 1024 + col] = pk2(v0 - vh0, v1 - vh1);
        *(uint32_t*)&Ctx[row0 + 2048 + col] = pk2(vh0, vh1);
        *(uint32_t*)&Ctx[row1 + col]        = pk2(wh0, wh1);
        *(uint32_t*)&Ctx[row1 + 1024 + col] = pk2(w0 - wh0, w1 - wh1);
        *(uint32_t*)&Ctx[row1 + 2048 + col] = pk2(wh0, wh1);
    }
}

// ------------------------- launch -------------------------
extern "C" void kernel_launch(void* const* d_in, const int* in_sizes, int n_in,
                              void* d_out, int out_size)
{
    const float* key   = (const float*)d_in[0];
    const float* value = (const float*)d_in[1];
    const float* query = (const float*)d_in[2];
    const float* wq = (const float*)d_in[3];
    const float* bq = (const float*)d_in[4];
    const float* wk = (const float*)d_in[5];
    const float* bk = (const float*)d_in[6];
    const float* wv = (const float*)d_in[7];
    const float* bv = (const float*)d_in[8];
    const float* wo = (const float*)d_in[9];
    const float* bo = (const float*)d_in[10];
    float* out = (float*)d_out;

    bf16 *xp, *wt, *qp, *kp, *vt;
    cudaGetSymbolAddress((void**)&xp, g_Xp);
    cudaGetSymbolAddress((void**)&wt, g_Wt);
    cudaGetSymbolAddress((void**)&qp, g_Qp);
    cudaGetSymbolAddress((void**)&kp, g_Kp);
    cudaGetSymbolAddress((void**)&vt, g_Vt);

    constexpr int SMG  = 128 * STG_STR * 4;         // 132096 (>= 2*BUFA+2*BUFB=110592)
    constexpr int SMFL = KBUF + 2 * VBUF;           // 120832
    cudaFuncSetAttribute(gemm_u,  cudaFuncAttributeMaxDynamicSharedMemorySize, SMG);
    cudaFuncSetAttribute(flash_k, cudaFuncAttributeMaxDynamicSharedMemorySize, SMFL);

    pack_wt_k<<<dim3(32, 32, 4), 256>>>(wq, wk, wv, wo, wt);
    pack_a_k<<<dim3(MTOT * HH / 1024, 3), 256>>>(query, key, value, xp);

    // merged QKV projections (z: 0=Q,1=K,2=Vt), CTA 128x256
    gemm_u<<<dim3(4, 64, 3), 256, SMG>>>(xp, wt, nullptr, qp, kp, vt,
                                         bq, bk, bv, -1);

    // fused attention -> packed ctx in Xp slab 0
    flash_k<<<dim3(16, 64), 256, SMFL>>>(qp, kp, vt, xp);

    // output projection
    gemm_u<<<dim3(4, 64, 1), 256, SMG>>>(xp, wt + 3 * WSLAB, out,
                                         nullptr, nullptr, nullptr,
                                         bo, bo, bo, 3);
}